// round 7
// baseline (speedup 1.0000x reference)
#include <cuda_runtime.h>
#include <cuda_fp16.h>
#include <cstdint>
#include <math.h>

#define NMAX   100000
#define EMAX   3400000
#define NFEAT  256
#define NHID   64
#define NHEADS 3
#define F1     192      // NHEADS*NHID
#define NCLASS 40

// ---------------- scratch (device globals; no allocations allowed) ----------
__device__ __align__(16) float   g_h   [NMAX * F1];     // fp32 (fdot1)
__device__ __align__(16) __half  g_hb  [NMAX * F1];     // fp16 mirror (agg1)
__device__ __align__(16) float   g_out1[NMAX * F1];     // layer1 out
__device__ __align__(16) float   g_h2  [NMAX * NCLASS]; // fp32 (fdot2)
__device__ __align__(16) __half  g_h2b [NMAX * NCLASS]; // fp16 mirror (agg2)
__device__ float g_fd  [NMAX * NHEADS];
__device__ float g_fs  [NMAX * NHEADS];
__device__ float g_f2d [NMAX];
__device__ float g_f2s [NMAX];

__device__ int   g_is64;
__device__ int   g_cnt    [NMAX];
__device__ int   g_rowptr [NMAX + 1];
__device__ int   g_cursor [NMAX];
__device__ int   g_part   [128];
__device__ int   g_total;
__device__ int   g_csr_src[EMAX];
__device__ int   g_epos   [EMAX];
__device__ __align__(16) float g_csr_w [EMAX * 3];
__device__ float g_csr_w2[EMAX];

__device__ __forceinline__ float elu1(float x) { return x > 0.f ? x : expm1f(x); }
__device__ __forceinline__ float att_w(float l) {
    float lr = l > 0.f ? l : 0.2f * l;
    return expf(-lr);
}

__device__ __forceinline__ int edge_at(const void* ei, long idx, int is64) {
    if (is64) return (int)((const long long*)ei)[idx];
    return ((const int*)ei)[idx];
}

__device__ __forceinline__ float tf32r(float x) {
    float r;
    asm("cvt.rna.tf32.f32 %0, %1;" : "=f"(r) : "f"(x));
    return r;
}

// ---------------- dtype detection -------------------------------------------
__global__ void detect_kernel(const int* __restrict__ ei32) {
    g_is64 = (ei32[1] == 0 && ei32[3] == 0 && ei32[5] == 0) ? 1 : 0;
}

// ---------------- CSR build --------------------------------------------------
__global__ void zero_cnt_kernel(int n) {
    int i = blockIdx.x * blockDim.x + threadIdx.x;
    if (i < n) g_cnt[i] = 0;
}

__global__ void count_kernel(const void* __restrict__ ei, int E) {
    int e = blockIdx.x * blockDim.x + threadIdx.x;
    if (e >= E) return;
    int is64 = g_is64;
    atomicAdd(&g_cnt[edge_at(ei, e, is64)], 1);
}

__global__ __launch_bounds__(1024) void scanA_kernel(int n) {
    __shared__ int sh[1024];
    int t = threadIdx.x;
    int i = blockIdx.x * 1024 + t;
    int v = (i < n) ? g_cnt[i] : 0;
    sh[t] = v;
    __syncthreads();
#pragma unroll
    for (int off = 1; off < 1024; off <<= 1) {
        int x = sh[t];
        int y = (t >= off) ? sh[t - off] : 0;
        __syncthreads();
        sh[t] = x + y;
        __syncthreads();
    }
    if (i < n) g_rowptr[i] = sh[t] - v;
    if (t == 1023) g_part[blockIdx.x] = sh[1023];
}

__global__ __launch_bounds__(128) void scanB_kernel(int nb) {
    __shared__ int sh[128];
    int t = threadIdx.x;
    int v = (t < nb) ? g_part[t] : 0;
    sh[t] = v;
    __syncthreads();
#pragma unroll
    for (int off = 1; off < 128; off <<= 1) {
        int x = sh[t];
        int y = (t >= off) ? sh[t - off] : 0;
        __syncthreads();
        sh[t] = x + y;
        __syncthreads();
    }
    g_part[t] = sh[t] - v;
    if (t == 127) g_total = sh[127];
}

__global__ __launch_bounds__(1024) void scanC_kernel(int n) {
    int i = blockIdx.x * 1024 + threadIdx.x;
    if (i < n) {
        int r = g_rowptr[i] + g_part[blockIdx.x];
        g_rowptr[i] = r;
        g_cursor[i] = r;
    }
    if (i == 0) g_rowptr[n] = g_total;
}

__global__ void scatter_kernel(const void* __restrict__ ei, int E) {
    int e = blockIdx.x * blockDim.x + threadIdx.x;
    if (e >= E) return;
    int is64 = g_is64;
    int dst = edge_at(ei, e, is64);
    int src = edge_at(ei, (long)E + e, is64);
    int pos = atomicAdd(&g_cursor[dst], 1);
    g_csr_src[pos] = src;
    g_epos[e] = pos;
#pragma unroll
    for (int h = 0; h < 3; h++)
        g_csr_w[pos * 3 + h] = att_w(g_fd[dst * 3 + h] + g_fs[src * 3 + h]);
}

__global__ void weight2_kernel(const void* __restrict__ ei, int E) {
    int e = blockIdx.x * blockDim.x + threadIdx.x;
    if (e >= E) return;
    int is64 = g_is64;
    int dst = edge_at(ei, e, is64);
    int src = edge_at(ei, (long)E + e, is64);
    g_csr_w2[g_epos[e]] = att_w(g_f2d[dst] + g_f2s[src]);
}

// ---------------- GEMM1 (tf32 tensor cores) --------------------------------
#define AS_S 36
#define BS_S 72
__global__ __launch_bounds__(256) void gemm1_tc_kernel(
    const float* __restrict__ x, const float* __restrict__ W, int n)
{
    __shared__ float As[128 * AS_S];
    __shared__ float Bs[32 * BS_S];

    const int head = blockIdx.y;
    const int m0   = blockIdx.x * 128;
    const int tid  = threadIdx.x;
    const float* Wb = W + head * NFEAT * NHID;

    const int wid   = tid >> 5;
    const int lane  = tid & 31;
    const int warpM = wid & 3;
    const int warpN = wid >> 2;
    const int g     = lane >> 2;
    const int tg    = lane & 3;

    float c[2][4][4];
#pragma unroll
    for (int mt = 0; mt < 2; mt++)
#pragma unroll
        for (int nt = 0; nt < 4; nt++)
#pragma unroll
            for (int r = 0; r < 4; r++) c[mt][nt][r] = 0.f;

    for (int kt = 0; kt < NFEAT; kt += 32) {
#pragma unroll
        for (int it = 0; it < 4; it++) {
            int j   = tid + it * 256;
            int row = j >> 3;
            int c4  = (j & 7) * 4;
            int gm  = m0 + row;
            float4 v = make_float4(0.f, 0.f, 0.f, 0.f);
            if (gm < n) v = *(const float4*)(x + (long)gm * NFEAT + kt + c4);
            v.x = tf32r(v.x); v.y = tf32r(v.y); v.z = tf32r(v.z); v.w = tf32r(v.w);
            *(float4*)&As[row * AS_S + c4] = v;
        }
#pragma unroll
        for (int it = 0; it < 2; it++) {
            int j   = tid + it * 256;
            int row = j >> 4;
            int c4  = (j & 15) * 4;
            float4 v = *(const float4*)(Wb + (kt + row) * NHID + c4);
            v.x = tf32r(v.x); v.y = tf32r(v.y); v.z = tf32r(v.z); v.w = tf32r(v.w);
            *(float4*)&Bs[row * BS_S + c4] = v;
        }
        __syncthreads();

#pragma unroll
        for (int ks = 0; ks < 4; ks++) {
            const int k0 = ks * 8;
            uint32_t a[2][4];
#pragma unroll
            for (int mt = 0; mt < 2; mt++) {
                int rbase = warpM * 32 + mt * 16;
                a[mt][0] = __float_as_uint(As[(rbase + g)     * AS_S + k0 + tg]);
                a[mt][1] = __float_as_uint(As[(rbase + g + 8) * AS_S + k0 + tg]);
                a[mt][2] = __float_as_uint(As[(rbase + g)     * AS_S + k0 + tg + 4]);
                a[mt][3] = __float_as_uint(As[(rbase + g + 8) * AS_S + k0 + tg + 4]);
            }
            uint32_t b[4][2];
#pragma unroll
            for (int nt = 0; nt < 4; nt++) {
                int cbase = warpN * 32 + nt * 8;
                b[nt][0] = __float_as_uint(Bs[(k0 + tg)     * BS_S + cbase + g]);
                b[nt][1] = __float_as_uint(Bs[(k0 + tg + 4) * BS_S + cbase + g]);
            }
#pragma unroll
            for (int mt = 0; mt < 2; mt++)
#pragma unroll
                for (int nt = 0; nt < 4; nt++) {
                    asm volatile(
                        "mma.sync.aligned.m16n8k8.row.col.f32.tf32.tf32.f32 "
                        "{%0,%1,%2,%3}, {%4,%5,%6,%7}, {%8,%9}, {%0,%1,%2,%3};"
                        : "+f"(c[mt][nt][0]), "+f"(c[mt][nt][1]),
                          "+f"(c[mt][nt][2]), "+f"(c[mt][nt][3])
                        : "r"(a[mt][0]), "r"(a[mt][1]), "r"(a[mt][2]), "r"(a[mt][3]),
                          "r"(b[nt][0]), "r"(b[nt][1]));
                }
        }
        __syncthreads();
    }

    // epilogue: fp32 master + fp16 mirror
#pragma unroll
    for (int mt = 0; mt < 2; mt++) {
        int row0 = m0 + warpM * 32 + mt * 16 + g;
#pragma unroll
        for (int nt = 0; nt < 4; nt++) {
            int col = head * NHID + warpN * 32 + nt * 8 + tg * 2;
            if (row0 < n) {
                *(float2*)(g_h + (long)row0 * F1 + col) = make_float2(c[mt][nt][0], c[mt][nt][1]);
                *(__half2*)(g_hb + (long)row0 * F1 + col) =
                    __floats2half2_rn(c[mt][nt][0], c[mt][nt][1]);
            }
            if (row0 + 8 < n) {
                *(float2*)(g_h + (long)(row0 + 8) * F1 + col) = make_float2(c[mt][nt][2], c[mt][nt][3]);
                *(__half2*)(g_hb + (long)(row0 + 8) * F1 + col) =
                    __floats2half2_rn(c[mt][nt][2], c[mt][nt][3]);
            }
        }
    }
}

// ---------------- fdot1 (fp32 h) -------------------------------------------
__global__ __launch_bounds__(256) void fdot1_kernel(
    const float* __restrict__ a1, const float* __restrict__ a2, int n)
{
    __shared__ float s1[F1], s2[F1];
    int tid = threadIdx.x;
    if (tid < F1) { s1[tid] = a1[tid]; s2[tid] = a2[tid]; }
    __syncthreads();

    int node = blockIdx.x * 8 + (tid >> 5);
    int lane = tid & 31;
    bool valid = node < n;
    int nclamp = valid ? node : (n - 1);
    const float* hr = g_h + (long)nclamp * F1;

    float d[3], s[3];
#pragma unroll
    for (int h = 0; h < 3; h++) {
        int i0 = h * 64 + lane;
        int i1 = h * 64 + 32 + lane;
        float v0 = hr[i0], v1 = hr[i1];
        d[h] = v0 * s1[i0] + v1 * s1[i1];
        s[h] = v0 * s2[i0] + v1 * s2[i1];
    }
#pragma unroll
    for (int off = 16; off > 0; off >>= 1) {
#pragma unroll
        for (int h = 0; h < 3; h++) {
            d[h] += __shfl_xor_sync(0xffffffffu, d[h], off);
            s[h] += __shfl_xor_sync(0xffffffffu, s[h], off);
        }
    }
    if (valid && lane == 0) {
#pragma unroll
        for (int h = 0; h < 3; h++) {
            g_fd[node * 3 + h] = d[h];
            g_fs[node * 3 + h] = s[h];
        }
    }
}

// ---------------- layer1 aggregation (fp16 gather) -------------------------
__global__ __launch_bounds__(64) void agg1_kernel(int n) {
    int node = blockIdx.x;
    if (node >= n) return;
    int t = threadIdx.x;
    int rs = g_rowptr[node];
    int re = g_rowptr[node + 1];
    bool active = t < 48;
    int head = t >> 4;

    float ax = 0.f, ay = 0.f, az = 0.f, aw = 0.f, den = 0.f;
    int j = rs;
    for (; j + 1 < re; j += 2) {
        int s0 = g_csr_src[j];
        int s1 = g_csr_src[j + 1];
        if (active) {
            float w0 = g_csr_w[j * 3 + head];
            float w1 = g_csr_w[(j + 1) * 3 + head];
            uint2 r0 = *(const uint2*)(g_hb + (long)s0 * F1 + t * 4);
            uint2 r1 = *(const uint2*)(g_hb + (long)s1 * F1 + t * 4);
            float2 p0 = __half22float2(*(__half2*)&r0.x);
            float2 p1 = __half22float2(*(__half2*)&r0.y);
            float2 q0 = __half22float2(*(__half2*)&r1.x);
            float2 q1 = __half22float2(*(__half2*)&r1.y);
            ax += w0 * p0.x + w1 * q0.x;
            ay += w0 * p0.y + w1 * q0.y;
            az += w0 * p1.x + w1 * q1.x;
            aw += w0 * p1.y + w1 * q1.y;
            den += w0 + w1;
        }
    }
    if (j < re) {
        int s0 = g_csr_src[j];
        if (active) {
            float w = g_csr_w[j * 3 + head];
            uint2 r0 = *(const uint2*)(g_hb + (long)s0 * F1 + t * 4);
            float2 p0 = __half22float2(*(__half2*)&r0.x);
            float2 p1 = __half22float2(*(__half2*)&r0.y);
            ax += w * p0.x; ay += w * p0.y; az += w * p1.x; aw += w * p1.y;
            den += w;
        }
    }
    if (active) {
        float inv = 1.0f / (den + 1e-16f);
        float4 r;
        r.x = elu1(ax * inv);
        r.y = elu1(ay * inv);
        r.z = elu1(az * inv);
        r.w = elu1(aw * inv);
        *(float4*)(g_out1 + (long)node * F1 + t * 4) = r;
    }
}

// ---------------- GEMM2 ----------------------------------------------------
__global__ __launch_bounds__(256) void gemm2_kernel(const float* __restrict__ Wo, int n) {
    __shared__ float As2[16][192];
    __shared__ float Ws[40][196];
    int tid = threadIdx.x;
    int r0  = blockIdx.x * 16;

    for (int i = tid; i < F1 * NCLASS; i += 256) {
        int k = i / NCLASS, c = i % NCLASS;
        Ws[c][k] = Wo[i];
    }
    for (int j = tid; j < 16 * 48; j += 256) {
        int row = j / 48;
        int c4  = (j % 48) * 4;
        int gm  = r0 + row;
        float4 v = make_float4(0.f, 0.f, 0.f, 0.f);
        if (gm < n) v = *(const float4*)(g_out1 + (long)gm * F1 + c4);
        *(float4*)&As2[row][c4] = v;
    }
    __syncthreads();

#pragma unroll
    for (int it = 0; it < 3; it++) {
        int o = tid + it * 256;
        if (o < 16 * NCLASS) {
            int r = o / NCLASS, c = o % NCLASS;
            const float4* a4 = (const float4*)As2[r];
            const float4* w4 = (const float4*)Ws[c];
            float acc = 0.f;
#pragma unroll
            for (int k = 0; k < 48; k++) {
                float4 a = a4[k], w = w4[k];
                acc += a.x * w.x + a.y * w.y + a.z * w.z + a.w * w.w;
            }
            int gm = r0 + r;
            if (gm < n) {
                g_h2 [(long)gm * NCLASS + c] = acc;
                g_h2b[(long)gm * NCLASS + c] = __float2half(acc);
            }
        }
    }
}

// ---------------- fdot2 (fp32 h2) ------------------------------------------
__global__ void fdot2_kernel(const float* __restrict__ a1o,
                             const float* __restrict__ a2o, int n)
{
    __shared__ float s1[NCLASS], s2[NCLASS];
    int tid = threadIdx.x;
    if (tid < NCLASS) { s1[tid] = a1o[tid]; s2[tid] = a2o[tid]; }
    __syncthreads();
    int node = blockIdx.x * blockDim.x + tid;
    if (node >= n) return;
    const float4* hr = (const float4*)(g_h2 + (long)node * NCLASS);
    float d = 0.f, s = 0.f;
#pragma unroll
    for (int q = 0; q < 10; q++) {
        float4 v = hr[q];
        d += v.x * s1[q * 4 + 0] + v.y * s1[q * 4 + 1] + v.z * s1[q * 4 + 2] + v.w * s1[q * 4 + 3];
        s += v.x * s2[q * 4 + 0] + v.y * s2[q * 4 + 1] + v.z * s2[q * 4 + 2] + v.w * s2[q * 4 + 3];
    }
    g_f2d[node] = d;
    g_f2s[node] = s;
}

// ---------------- layer2 aggregation (fp16 gather) -------------------------
__global__ __launch_bounds__(64) void agg2_kernel(float* __restrict__ out, int n) {
    int node = blockIdx.x;
    if (node >= n) return;
    int t = threadIdx.x;
    int rs = g_rowptr[node];
    int re = g_rowptr[node + 1];
    bool active = t < 20;       // each thread owns 2 classes (half2)

    float a0 = 0.f, a1 = 0.f, den = 0.f;
    int j = rs;
    for (; j + 1 < re; j += 2) {
        float w0 = g_csr_w2[j];
        float w1 = g_csr_w2[j + 1];
        int s0 = g_csr_src[j];
        int s1 = g_csr_src[j + 1];
        if (active) {
            float2 p = __half22float2(*(const __half2*)(g_h2b + (long)s0 * NCLASS + t * 2));
            float2 q = __half22float2(*(const __half2*)(g_h2b + (long)s1 * NCLASS + t * 2));
            a0 += w0 * p.x + w1 * q.x;
            a1 += w0 * p.y + w1 * q.y;
            den += w0 + w1;
        }
    }
    if (j < re) {
        float w = g_csr_w2[j];
        int s0 = g_csr_src[j];
        if (active) {
            float2 p = __half22float2(*(const __half2*)(g_h2b + (long)s0 * NCLASS + t * 2));
            a0 += w * p.x;
            a1 += w * p.y;
            den += w;
        }
    }
    if (active) {
        float inv = 1.0f / (den + 1e-16f);
        float2 r = make_float2(elu1(a0 * inv), elu1(a1 * inv));
        *(float2*)(out + (long)node * NCLASS + t * 2) = r;
    }
}

// ---------------- launch ---------------------------------------------------
extern "C" void kernel_launch(void* const* d_in, const int* in_sizes, int n_in,
                              void* d_out, int out_size)
{
    const float* x   = (const float*)d_in[0];
    const void*  ei  = d_in[1];
    const float* W   = (const float*)d_in[2];
    const float* a1  = (const float*)d_in[3];
    const float* a2  = (const float*)d_in[4];
    const float* Wo  = (const float*)d_in[5];
    const float* a1o = (const float*)d_in[6];
    const float* a2o = (const float*)d_in[7];
    float* out = (float*)d_out;

    int n = in_sizes[0] / NFEAT;     // 100000
    int E = in_sizes[1] / 2;         // 3300000
    int nb = (n + 1023) / 1024;

    detect_kernel<<<1, 1>>>((const int*)ei);

    // CSR structure build
    zero_cnt_kernel<<<(n + 1023) / 1024, 1024>>>(n);
    count_kernel<<<(E + 255) / 256, 256>>>(ei, E);
    scanA_kernel<<<nb, 1024>>>(n);
    scanB_kernel<<<1, 128>>>(nb);
    scanC_kernel<<<nb, 1024>>>(n);

    // layer 1 dense
    dim3 g1((n + 127) / 128, NHEADS);
    gemm1_tc_kernel<<<g1, 256>>>(x, W, n);
    fdot1_kernel<<<(n + 7) / 8, 256>>>(a1, a2, n);

    // CSR scatter + layer1 edge weights
    scatter_kernel<<<(E + 255) / 256, 256>>>(ei, E);

    // layer1 aggregate
    agg1_kernel<<<n, 64>>>(n);

    // layer 2 dense
    gemm2_kernel<<<(n + 15) / 16, 256>>>(Wo, n);
    fdot2_kernel<<<(n + 255) / 256, 256>>>(a1o, a2o, n);

    // layer2 weights + aggregate
    weight2_kernel<<<(E + 255) / 256, 256>>>(ei, E);
    agg2_kernel<<<n, 64>>>(out, n);
}

// round 8
// speedup vs baseline: 1.1241x; 1.1241x over previous
#include <cuda_runtime.h>
#include <cstdint>
#include <math.h>

#define NMAX   100000
#define EMAX   3400000
#define NFEAT  256
#define NHID   64
#define NHEADS 3
#define F1     192      // NHEADS*NHID
#define NCLASS 40

// ---------------- scratch (device globals; no allocations allowed) ----------
__device__ __align__(16) float g_h   [NMAX * F1];
__device__ __align__(16) float g_out1[NMAX * F1];
__device__ __align__(16) float g_h2  [NMAX * NCLASS];
__device__ float g_fd  [NMAX * NHEADS];
__device__ float g_fs  [NMAX * NHEADS];
__device__ float g_f2d [NMAX];
__device__ float g_f2s [NMAX];

__device__ int   g_is64;
__device__ int   g_cnt    [NMAX];
__device__ int   g_rowptr [NMAX + 1];
__device__ int   g_cursor [NMAX];
__device__ int   g_part   [128];
__device__ int   g_total;
__device__ int   g_csr_src[EMAX];
__device__ __align__(16) float g_csr_w [EMAX * 3];

__device__ __forceinline__ float elu1(float x) { return x > 0.f ? x : expm1f(x); }
__device__ __forceinline__ float att_w(float l) {
    float lr = l > 0.f ? l : 0.2f * l;
    return expf(-lr);
}

__device__ __forceinline__ int edge_at(const void* ei, long idx, int is64) {
    if (is64) return (int)((const long long*)ei)[idx];
    return ((const int*)ei)[idx];
}

__device__ __forceinline__ float tf32r(float x) {
    float r;
    asm("cvt.rna.tf32.f32 %0, %1;" : "=f"(r) : "f"(x));
    return r;
}

// ---------------- dtype detection -------------------------------------------
__global__ void detect_kernel(const int* __restrict__ ei32) {
    g_is64 = (ei32[1] == 0 && ei32[3] == 0 && ei32[5] == 0) ? 1 : 0;
}

// ---------------- CSR build --------------------------------------------------
__global__ void zero_cnt_kernel(int n) {
    int i = blockIdx.x * blockDim.x + threadIdx.x;
    if (i < n) g_cnt[i] = 0;
}

__global__ void count_kernel(const void* __restrict__ ei, int E) {
    int e = blockIdx.x * blockDim.x + threadIdx.x;
    if (e >= E) return;
    int is64 = g_is64;
    atomicAdd(&g_cnt[edge_at(ei, e, is64)], 1);
}

__global__ __launch_bounds__(1024) void scanA_kernel(int n) {
    __shared__ int sh[1024];
    int t = threadIdx.x;
    int i = blockIdx.x * 1024 + t;
    int v = (i < n) ? g_cnt[i] : 0;
    sh[t] = v;
    __syncthreads();
#pragma unroll
    for (int off = 1; off < 1024; off <<= 1) {
        int x = sh[t];
        int y = (t >= off) ? sh[t - off] : 0;
        __syncthreads();
        sh[t] = x + y;
        __syncthreads();
    }
    if (i < n) g_rowptr[i] = sh[t] - v;
    if (t == 1023) g_part[blockIdx.x] = sh[1023];
}

__global__ __launch_bounds__(128) void scanB_kernel(int nb) {
    __shared__ int sh[128];
    int t = threadIdx.x;
    int v = (t < nb) ? g_part[t] : 0;
    sh[t] = v;
    __syncthreads();
#pragma unroll
    for (int off = 1; off < 128; off <<= 1) {
        int x = sh[t];
        int y = (t >= off) ? sh[t - off] : 0;
        __syncthreads();
        sh[t] = x + y;
        __syncthreads();
    }
    g_part[t] = sh[t] - v;
    if (t == 127) g_total = sh[127];
}

__global__ __launch_bounds__(1024) void scanC_kernel(int n) {
    int i = blockIdx.x * 1024 + threadIdx.x;
    if (i < n) {
        int r = g_rowptr[i] + g_part[blockIdx.x];
        g_rowptr[i] = r;
        g_cursor[i] = r;
    }
    if (i == 0) g_rowptr[n] = g_total;
}

// scatter + layer1 edge weights (no epos needed anymore)
__global__ void scatter_kernel(const void* __restrict__ ei, int E) {
    int e = blockIdx.x * blockDim.x + threadIdx.x;
    if (e >= E) return;
    int is64 = g_is64;
    int dst = edge_at(ei, e, is64);
    int src = edge_at(ei, (long)E + e, is64);
    int pos = atomicAdd(&g_cursor[dst], 1);
    g_csr_src[pos] = src;
#pragma unroll
    for (int h = 0; h < 3; h++)
        g_csr_w[pos * 3 + h] = att_w(g_fd[dst * 3 + h] + g_fs[src * 3 + h]);
}

// ---------------- GEMM1 (tf32 tensor cores) --------------------------------
#define AS_S 36
#define BS_S 72
__global__ __launch_bounds__(256) void gemm1_tc_kernel(
    const float* __restrict__ x, const float* __restrict__ W, int n)
{
    __shared__ float As[128 * AS_S];
    __shared__ float Bs[32 * BS_S];

    const int head = blockIdx.y;
    const int m0   = blockIdx.x * 128;
    const int tid  = threadIdx.x;
    const float* Wb = W + head * NFEAT * NHID;

    const int wid   = tid >> 5;
    const int lane  = tid & 31;
    const int warpM = wid & 3;
    const int warpN = wid >> 2;
    const int g     = lane >> 2;
    const int tg    = lane & 3;

    float c[2][4][4];
#pragma unroll
    for (int mt = 0; mt < 2; mt++)
#pragma unroll
        for (int nt = 0; nt < 4; nt++)
#pragma unroll
            for (int r = 0; r < 4; r++) c[mt][nt][r] = 0.f;

    for (int kt = 0; kt < NFEAT; kt += 32) {
#pragma unroll
        for (int it = 0; it < 4; it++) {
            int j   = tid + it * 256;
            int row = j >> 3;
            int c4  = (j & 7) * 4;
            int gm  = m0 + row;
            float4 v = make_float4(0.f, 0.f, 0.f, 0.f);
            if (gm < n) v = *(const float4*)(x + (long)gm * NFEAT + kt + c4);
            v.x = tf32r(v.x); v.y = tf32r(v.y); v.z = tf32r(v.z); v.w = tf32r(v.w);
            *(float4*)&As[row * AS_S + c4] = v;
        }
#pragma unroll
        for (int it = 0; it < 2; it++) {
            int j   = tid + it * 256;
            int row = j >> 4;
            int c4  = (j & 15) * 4;
            float4 v = *(const float4*)(Wb + (kt + row) * NHID + c4);
            v.x = tf32r(v.x); v.y = tf32r(v.y); v.z = tf32r(v.z); v.w = tf32r(v.w);
            *(float4*)&Bs[row * BS_S + c4] = v;
        }
        __syncthreads();

#pragma unroll
        for (int ks = 0; ks < 4; ks++) {
            const int k0 = ks * 8;
            uint32_t a[2][4];
#pragma unroll
            for (int mt = 0; mt < 2; mt++) {
                int rbase = warpM * 32 + mt * 16;
                a[mt][0] = __float_as_uint(As[(rbase + g)     * AS_S + k0 + tg]);
                a[mt][1] = __float_as_uint(As[(rbase + g + 8) * AS_S + k0 + tg]);
                a[mt][2] = __float_as_uint(As[(rbase + g)     * AS_S + k0 + tg + 4]);
                a[mt][3] = __float_as_uint(As[(rbase + g + 8) * AS_S + k0 + tg + 4]);
            }
            uint32_t b[4][2];
#pragma unroll
            for (int nt = 0; nt < 4; nt++) {
                int cbase = warpN * 32 + nt * 8;
                b[nt][0] = __float_as_uint(Bs[(k0 + tg)     * BS_S + cbase + g]);
                b[nt][1] = __float_as_uint(Bs[(k0 + tg + 4) * BS_S + cbase + g]);
            }
#pragma unroll
            for (int mt = 0; mt < 2; mt++)
#pragma unroll
                for (int nt = 0; nt < 4; nt++) {
                    asm volatile(
                        "mma.sync.aligned.m16n8k8.row.col.f32.tf32.tf32.f32 "
                        "{%0,%1,%2,%3}, {%4,%5,%6,%7}, {%8,%9}, {%0,%1,%2,%3};"
                        : "+f"(c[mt][nt][0]), "+f"(c[mt][nt][1]),
                          "+f"(c[mt][nt][2]), "+f"(c[mt][nt][3])
                        : "r"(a[mt][0]), "r"(a[mt][1]), "r"(a[mt][2]), "r"(a[mt][3]),
                          "r"(b[nt][0]), "r"(b[nt][1]));
                }
        }
        __syncthreads();
    }

#pragma unroll
    for (int mt = 0; mt < 2; mt++) {
        int row0 = m0 + warpM * 32 + mt * 16 + g;
#pragma unroll
        for (int nt = 0; nt < 4; nt++) {
            int col = head * NHID + warpN * 32 + nt * 8 + tg * 2;
            if (row0 < n)
                *(float2*)(g_h + (long)row0 * F1 + col) = make_float2(c[mt][nt][0], c[mt][nt][1]);
            if (row0 + 8 < n)
                *(float2*)(g_h + (long)(row0 + 8) * F1 + col) = make_float2(c[mt][nt][2], c[mt][nt][3]);
        }
    }
}

// ---------------- fdot1 ----------------------------------------------------
__global__ __launch_bounds__(256) void fdot1_kernel(
    const float* __restrict__ a1, const float* __restrict__ a2, int n)
{
    __shared__ float s1[F1], s2[F1];
    int tid = threadIdx.x;
    if (tid < F1) { s1[tid] = a1[tid]; s2[tid] = a2[tid]; }
    __syncthreads();

    int node = blockIdx.x * 8 + (tid >> 5);
    int lane = tid & 31;
    bool valid = node < n;
    int nclamp = valid ? node : (n - 1);
    const float* hr = g_h + (long)nclamp * F1;

    float d[3], s[3];
#pragma unroll
    for (int h = 0; h < 3; h++) {
        int i0 = h * 64 + lane;
        int i1 = h * 64 + 32 + lane;
        float v0 = hr[i0], v1 = hr[i1];
        d[h] = v0 * s1[i0] + v1 * s1[i1];
        s[h] = v0 * s2[i0] + v1 * s2[i1];
    }
#pragma unroll
    for (int off = 16; off > 0; off >>= 1) {
#pragma unroll
        for (int h = 0; h < 3; h++) {
            d[h] += __shfl_xor_sync(0xffffffffu, d[h], off);
            s[h] += __shfl_xor_sync(0xffffffffu, s[h], off);
        }
    }
    if (valid && lane == 0) {
#pragma unroll
        for (int h = 0; h < 3; h++) {
            g_fd[node * 3 + h] = d[h];
            g_fs[node * 3 + h] = s[h];
        }
    }
}

// ---------------- layer1 aggregation (fp32 gather, 4-edge unroll) ----------
__global__ __launch_bounds__(64) void agg1_kernel(int n) {
    int node = blockIdx.x;
    if (node >= n) return;
    int t = threadIdx.x;
    int rs = g_rowptr[node];
    int re = g_rowptr[node + 1];
    bool active = t < 48;
    int head = t >> 4;

    float ax = 0.f, ay = 0.f, az = 0.f, aw = 0.f, den = 0.f;
    int j = rs;
    for (; j + 3 < re; j += 4) {
        int s0 = g_csr_src[j];
        int s1 = g_csr_src[j + 1];
        int s2 = g_csr_src[j + 2];
        int s3 = g_csr_src[j + 3];
        if (active) {
            float w0 = g_csr_w[(j + 0) * 3 + head];
            float w1 = g_csr_w[(j + 1) * 3 + head];
            float w2 = g_csr_w[(j + 2) * 3 + head];
            float w3 = g_csr_w[(j + 3) * 3 + head];
            float4 v0 = *(const float4*)(g_h + (long)s0 * F1 + t * 4);
            float4 v1 = *(const float4*)(g_h + (long)s1 * F1 + t * 4);
            float4 v2 = *(const float4*)(g_h + (long)s2 * F1 + t * 4);
            float4 v3 = *(const float4*)(g_h + (long)s3 * F1 + t * 4);
            ax += w0 * v0.x + w1 * v1.x + w2 * v2.x + w3 * v3.x;
            ay += w0 * v0.y + w1 * v1.y + w2 * v2.y + w3 * v3.y;
            az += w0 * v0.z + w1 * v1.z + w2 * v2.z + w3 * v3.z;
            aw += w0 * v0.w + w1 * v1.w + w2 * v2.w + w3 * v3.w;
            den += (w0 + w1) + (w2 + w3);
        }
    }
    for (; j < re; j++) {
        int s0 = g_csr_src[j];
        if (active) {
            float  w = g_csr_w[j * 3 + head];
            float4 v = *(const float4*)(g_h + (long)s0 * F1 + t * 4);
            ax += w * v.x; ay += w * v.y; az += w * v.z; aw += w * v.w;
            den += w;
        }
    }
    if (active) {
        float inv = 1.0f / (den + 1e-16f);
        float4 r;
        r.x = elu1(ax * inv);
        r.y = elu1(ay * inv);
        r.z = elu1(az * inv);
        r.w = elu1(aw * inv);
        *(float4*)(g_out1 + (long)node * F1 + t * 4) = r;
    }
}

// ---------------- GEMM2 ----------------------------------------------------
__global__ __launch_bounds__(256) void gemm2_kernel(const float* __restrict__ Wo, int n) {
    __shared__ float As2[16][192];
    __shared__ float Ws[40][196];
    int tid = threadIdx.x;
    int r0  = blockIdx.x * 16;

    for (int i = tid; i < F1 * NCLASS; i += 256) {
        int k = i / NCLASS, c = i % NCLASS;
        Ws[c][k] = Wo[i];
    }
    for (int j = tid; j < 16 * 48; j += 256) {
        int row = j / 48;
        int c4  = (j % 48) * 4;
        int gm  = r0 + row;
        float4 v = make_float4(0.f, 0.f, 0.f, 0.f);
        if (gm < n) v = *(const float4*)(g_out1 + (long)gm * F1 + c4);
        *(float4*)&As2[row][c4] = v;
    }
    __syncthreads();

#pragma unroll
    for (int it = 0; it < 3; it++) {
        int o = tid + it * 256;
        if (o < 16 * NCLASS) {
            int r = o / NCLASS, c = o % NCLASS;
            const float4* a4 = (const float4*)As2[r];
            const float4* w4 = (const float4*)Ws[c];
            float acc = 0.f;
#pragma unroll
            for (int k = 0; k < 48; k++) {
                float4 a = a4[k], w = w4[k];
                acc += a.x * w.x + a.y * w.y + a.z * w.z + a.w * w.w;
            }
            int gm = r0 + r;
            if (gm < n) g_h2[(long)gm * NCLASS + c] = acc;
        }
    }
}

// ---------------- fdot2 ----------------------------------------------------
__global__ void fdot2_kernel(const float* __restrict__ a1o,
                             const float* __restrict__ a2o, int n)
{
    __shared__ float s1[NCLASS], s2[NCLASS];
    int tid = threadIdx.x;
    if (tid < NCLASS) { s1[tid] = a1o[tid]; s2[tid] = a2o[tid]; }
    __syncthreads();
    int node = blockIdx.x * blockDim.x + tid;
    if (node >= n) return;
    const float4* hr = (const float4*)(g_h2 + (long)node * NCLASS);
    float d = 0.f, s = 0.f;
#pragma unroll
    for (int q = 0; q < 10; q++) {
        float4 v = hr[q];
        d += v.x * s1[q * 4 + 0] + v.y * s1[q * 4 + 1] + v.z * s1[q * 4 + 2] + v.w * s1[q * 4 + 3];
        s += v.x * s2[q * 4 + 0] + v.y * s2[q * 4 + 1] + v.z * s2[q * 4 + 2] + v.w * s2[q * 4 + 3];
    }
    g_f2d[node] = d;
    g_f2s[node] = s;
}

// ---------------- layer2 aggregation (fused weights, warp per node) --------
__global__ __launch_bounds__(64) void agg2_kernel(float* __restrict__ out, int n) {
    int node = blockIdx.x * 2 + (threadIdx.x >> 5);
    if (node >= n) return;
    int lane = threadIdx.x & 31;
    int rs = g_rowptr[node];
    int re = g_rowptr[node + 1];
    bool active = lane < 20;            // 20 lanes x 2 classes
    float fd = g_f2d[node];

    float a0 = 0.f, a1 = 0.f, den = 0.f;
    int j = rs;
    for (; j + 1 < re; j += 2) {
        int s0 = g_csr_src[j];
        int s1 = g_csr_src[j + 1];
        float w0 = 0.f, w1 = 0.f;
        if (lane == 0) {
            w0 = att_w(fd + g_f2s[s0]);
            w1 = att_w(fd + g_f2s[s1]);
        }
        w0 = __shfl_sync(0xffffffffu, w0, 0);
        w1 = __shfl_sync(0xffffffffu, w1, 0);
        if (active) {
            float2 p = *(const float2*)(g_h2 + (long)s0 * NCLASS + lane * 2);
            float2 q = *(const float2*)(g_h2 + (long)s1 * NCLASS + lane * 2);
            a0 += w0 * p.x + w1 * q.x;
            a1 += w0 * p.y + w1 * q.y;
            den += w0 + w1;
        }
    }
    if (j < re) {
        int s0 = g_csr_src[j];
        float w = 0.f;
        if (lane == 0) w = att_w(fd + g_f2s[s0]);
        w = __shfl_sync(0xffffffffu, w, 0);
        if (active) {
            float2 p = *(const float2*)(g_h2 + (long)s0 * NCLASS + lane * 2);
            a0 += w * p.x;
            a1 += w * p.y;
            den += w;
        }
    }
    if (active) {
        float inv = 1.0f / (den + 1e-16f);
        float2 r = make_float2(elu1(a0 * inv), elu1(a1 * inv));
        *(float2*)(out + (long)node * NCLASS + lane * 2) = r;
    }
}

// ---------------- launch ---------------------------------------------------
extern "C" void kernel_launch(void* const* d_in, const int* in_sizes, int n_in,
                              void* d_out, int out_size)
{
    const float* x   = (const float*)d_in[0];
    const void*  ei  = d_in[1];
    const float* W   = (const float*)d_in[2];
    const float* a1  = (const float*)d_in[3];
    const float* a2  = (const float*)d_in[4];
    const float* Wo  = (const float*)d_in[5];
    const float* a1o = (const float*)d_in[6];
    const float* a2o = (const float*)d_in[7];
    float* out = (float*)d_out;

    int n = in_sizes[0] / NFEAT;     // 100000
    int E = in_sizes[1] / 2;         // 3300000
    int nb = (n + 1023) / 1024;

    detect_kernel<<<1, 1>>>((const int*)ei);

    // CSR structure build
    zero_cnt_kernel<<<(n + 1023) / 1024, 1024>>>(n);
    count_kernel<<<(E + 255) / 256, 256>>>(ei, E);
    scanA_kernel<<<nb, 1024>>>(n);
    scanB_kernel<<<1, 128>>>(nb);
    scanC_kernel<<<nb, 1024>>>(n);

    // layer 1 dense
    dim3 g1((n + 127) / 128, NHEADS);
    gemm1_tc_kernel<<<g1, 256>>>(x, W, n);
    fdot1_kernel<<<(n + 7) / 8, 256>>>(a1, a2, n);

    // CSR scatter + layer1 edge weights
    scatter_kernel<<<(E + 255) / 256, 256>>>(ei, E);

    // layer1 aggregate
    agg1_kernel<<<n, 64>>>(n);

    // layer 2 dense
    gemm2_kernel<<<(n + 15) / 16, 256>>>(Wo, n);
    fdot2_kernel<<<(n + 255) / 256, 256>>>(a1o, a2o, n);

    // layer2 aggregate (weights fused in)
    agg2_kernel<<<(n + 1) / 2, 64>>>(out, n);
}

// round 9
// speedup vs baseline: 1.1893x; 1.0580x over previous
#include <cuda_runtime.h>
#include <cstdint>
#include <math.h>

#define NMAX   100000
#define EMAX   3400000
#define NFEAT  256
#define NHID   64
#define NHEADS 3
#define F1     192      // NHEADS*NHID
#define NCLASS 40

// ---------------- scratch (device globals; no allocations allowed) ----------
__device__ __align__(16) float g_h   [NMAX * F1];
__device__ __align__(16) float g_out1[NMAX * F1];
__device__ __align__(16) float g_h2  [NMAX * NCLASS];
__device__ float g_fd  [NMAX * NHEADS];
__device__ float g_fs  [NMAX * NHEADS];
__device__ float g_f2d [NMAX];
__device__ float g_f2s [NMAX];

__device__ int   g_is64;
__device__ int   g_cnt    [NMAX];
__device__ int   g_rowptr [NMAX + 1];
__device__ int   g_cursor [NMAX];
__device__ int   g_part   [128];
__device__ int   g_total;
__device__ int   g_csr_src[EMAX];
__device__ __align__(16) float g_csr_w [EMAX * 3];

__device__ __forceinline__ float elu1(float x) { return x > 0.f ? x : expm1f(x); }
__device__ __forceinline__ float att_w(float l) {
    float lr = l > 0.f ? l : 0.2f * l;
    return expf(-lr);
}

__device__ __forceinline__ int edge_at(const void* ei, long idx, int is64) {
    if (is64) return (int)((const long long*)ei)[idx];
    return ((const int*)ei)[idx];
}

__device__ __forceinline__ float tf32r(float x) {
    float r;
    asm("cvt.rna.tf32.f32 %0, %1;" : "=f"(r) : "f"(x));
    return r;
}

// ---------------- dtype detection -------------------------------------------
__global__ void detect_kernel(const int* __restrict__ ei32) {
    g_is64 = (ei32[1] == 0 && ei32[3] == 0 && ei32[5] == 0) ? 1 : 0;
}

// ---------------- CSR build --------------------------------------------------
__global__ void zero_cnt_kernel(int n) {
    int i = blockIdx.x * blockDim.x + threadIdx.x;
    if (i < n) g_cnt[i] = 0;
}

__global__ void count_kernel(const void* __restrict__ ei, int E) {
    int e = blockIdx.x * blockDim.x + threadIdx.x;
    if (e >= E) return;
    int is64 = g_is64;
    atomicAdd(&g_cnt[edge_at(ei, e, is64)], 1);
}

__global__ __launch_bounds__(1024) void scanA_kernel(int n) {
    __shared__ int sh[1024];
    int t = threadIdx.x;
    int i = blockIdx.x * 1024 + t;
    int v = (i < n) ? g_cnt[i] : 0;
    sh[t] = v;
    __syncthreads();
#pragma unroll
    for (int off = 1; off < 1024; off <<= 1) {
        int x = sh[t];
        int y = (t >= off) ? sh[t - off] : 0;
        __syncthreads();
        sh[t] = x + y;
        __syncthreads();
    }
    if (i < n) g_rowptr[i] = sh[t] - v;
    if (t == 1023) g_part[blockIdx.x] = sh[1023];
}

__global__ __launch_bounds__(128) void scanB_kernel(int nb) {
    __shared__ int sh[128];
    int t = threadIdx.x;
    int v = (t < nb) ? g_part[t] : 0;
    sh[t] = v;
    __syncthreads();
#pragma unroll
    for (int off = 1; off < 128; off <<= 1) {
        int x = sh[t];
        int y = (t >= off) ? sh[t - off] : 0;
        __syncthreads();
        sh[t] = x + y;
        __syncthreads();
    }
    g_part[t] = sh[t] - v;
    if (t == 127) g_total = sh[127];
}

__global__ __launch_bounds__(1024) void scanC_kernel(int n) {
    int i = blockIdx.x * 1024 + threadIdx.x;
    if (i < n) {
        int r = g_rowptr[i] + g_part[blockIdx.x];
        g_rowptr[i] = r;
        g_cursor[i] = r;
    }
    if (i == 0) g_rowptr[n] = g_total;
}

// scatter + layer1 edge weights
__global__ void scatter_kernel(const void* __restrict__ ei, int E) {
    int e = blockIdx.x * blockDim.x + threadIdx.x;
    if (e >= E) return;
    int is64 = g_is64;
    int dst = edge_at(ei, e, is64);
    int src = edge_at(ei, (long)E + e, is64);
    int pos = atomicAdd(&g_cursor[dst], 1);
    g_csr_src[pos] = src;
#pragma unroll
    for (int h = 0; h < 3; h++)
        g_csr_w[pos * 3 + h] = att_w(g_fd[dst * 3 + h] + g_fs[src * 3 + h]);
}

// ---------------- GEMM1 (tf32 tensor cores) --------------------------------
#define AS_S 36
#define BS_S 72
__global__ __launch_bounds__(256) void gemm1_tc_kernel(
    const float* __restrict__ x, const float* __restrict__ W, int n)
{
    __shared__ float As[128 * AS_S];
    __shared__ float Bs[32 * BS_S];

    const int head = blockIdx.y;
    const int m0   = blockIdx.x * 128;
    const int tid  = threadIdx.x;
    const float* Wb = W + head * NFEAT * NHID;

    const int wid   = tid >> 5;
    const int lane  = tid & 31;
    const int warpM = wid & 3;
    const int warpN = wid >> 2;
    const int g     = lane >> 2;
    const int tg    = lane & 3;

    float c[2][4][4];
#pragma unroll
    for (int mt = 0; mt < 2; mt++)
#pragma unroll
        for (int nt = 0; nt < 4; nt++)
#pragma unroll
            for (int r = 0; r < 4; r++) c[mt][nt][r] = 0.f;

    for (int kt = 0; kt < NFEAT; kt += 32) {
#pragma unroll
        for (int it = 0; it < 4; it++) {
            int j   = tid + it * 256;
            int row = j >> 3;
            int c4  = (j & 7) * 4;
            int gm  = m0 + row;
            float4 v = make_float4(0.f, 0.f, 0.f, 0.f);
            if (gm < n) v = *(const float4*)(x + (long)gm * NFEAT + kt + c4);
            v.x = tf32r(v.x); v.y = tf32r(v.y); v.z = tf32r(v.z); v.w = tf32r(v.w);
            *(float4*)&As[row * AS_S + c4] = v;
        }
#pragma unroll
        for (int it = 0; it < 2; it++) {
            int j   = tid + it * 256;
            int row = j >> 4;
            int c4  = (j & 15) * 4;
            float4 v = *(const float4*)(Wb + (kt + row) * NHID + c4);
            v.x = tf32r(v.x); v.y = tf32r(v.y); v.z = tf32r(v.z); v.w = tf32r(v.w);
            *(float4*)&Bs[row * BS_S + c4] = v;
        }
        __syncthreads();

#pragma unroll
        for (int ks = 0; ks < 4; ks++) {
            const int k0 = ks * 8;
            uint32_t a[2][4];
#pragma unroll
            for (int mt = 0; mt < 2; mt++) {
                int rbase = warpM * 32 + mt * 16;
                a[mt][0] = __float_as_uint(As[(rbase + g)     * AS_S + k0 + tg]);
                a[mt][1] = __float_as_uint(As[(rbase + g + 8) * AS_S + k0 + tg]);
                a[mt][2] = __float_as_uint(As[(rbase + g)     * AS_S + k0 + tg + 4]);
                a[mt][3] = __float_as_uint(As[(rbase + g + 8) * AS_S + k0 + tg + 4]);
            }
            uint32_t b[4][2];
#pragma unroll
            for (int nt = 0; nt < 4; nt++) {
                int cbase = warpN * 32 + nt * 8;
                b[nt][0] = __float_as_uint(Bs[(k0 + tg)     * BS_S + cbase + g]);
                b[nt][1] = __float_as_uint(Bs[(k0 + tg + 4) * BS_S + cbase + g]);
            }
#pragma unroll
            for (int mt = 0; mt < 2; mt++)
#pragma unroll
                for (int nt = 0; nt < 4; nt++) {
                    asm volatile(
                        "mma.sync.aligned.m16n8k8.row.col.f32.tf32.tf32.f32 "
                        "{%0,%1,%2,%3}, {%4,%5,%6,%7}, {%8,%9}, {%0,%1,%2,%3};"
                        : "+f"(c[mt][nt][0]), "+f"(c[mt][nt][1]),
                          "+f"(c[mt][nt][2]), "+f"(c[mt][nt][3])
                        : "r"(a[mt][0]), "r"(a[mt][1]), "r"(a[mt][2]), "r"(a[mt][3]),
                          "r"(b[nt][0]), "r"(b[nt][1]));
                }
        }
        __syncthreads();
    }

#pragma unroll
    for (int mt = 0; mt < 2; mt++) {
        int row0 = m0 + warpM * 32 + mt * 16 + g;
#pragma unroll
        for (int nt = 0; nt < 4; nt++) {
            int col = head * NHID + warpN * 32 + nt * 8 + tg * 2;
            if (row0 < n)
                *(float2*)(g_h + (long)row0 * F1 + col) = make_float2(c[mt][nt][0], c[mt][nt][1]);
            if (row0 + 8 < n)
                *(float2*)(g_h + (long)(row0 + 8) * F1 + col) = make_float2(c[mt][nt][2], c[mt][nt][3]);
        }
    }
}

// ---------------- fdot1 ----------------------------------------------------
__global__ __launch_bounds__(256) void fdot1_kernel(
    const float* __restrict__ a1, const float* __restrict__ a2, int n)
{
    __shared__ float s1[F1], s2[F1];
    int tid = threadIdx.x;
    if (tid < F1) { s1[tid] = a1[tid]; s2[tid] = a2[tid]; }
    __syncthreads();

    int node = blockIdx.x * 8 + (tid >> 5);
    int lane = tid & 31;
    bool valid = node < n;
    int nclamp = valid ? node : (n - 1);
    const float* hr = g_h + (long)nclamp * F1;

    float d[3], s[3];
#pragma unroll
    for (int h = 0; h < 3; h++) {
        int i0 = h * 64 + lane;
        int i1 = h * 64 + 32 + lane;
        float v0 = hr[i0], v1 = hr[i1];
        d[h] = v0 * s1[i0] + v1 * s1[i1];
        s[h] = v0 * s2[i0] + v1 * s2[i1];
    }
#pragma unroll
    for (int off = 16; off > 0; off >>= 1) {
#pragma unroll
        for (int h = 0; h < 3; h++) {
            d[h] += __shfl_xor_sync(0xffffffffu, d[h], off);
            s[h] += __shfl_xor_sync(0xffffffffu, s[h], off);
        }
    }
    if (valid && lane == 0) {
#pragma unroll
        for (int h = 0; h < 3; h++) {
            g_fd[node * 3 + h] = d[h];
            g_fs[node * 3 + h] = s[h];
        }
    }
}

// ---------------- layer1 aggregation (fp32 gather, 8-edge unroll) ----------
__global__ __launch_bounds__(64) void agg1_kernel(int n) {
    int node = blockIdx.x;
    if (node >= n) return;
    int t = threadIdx.x;
    int rs = g_rowptr[node];
    int re = g_rowptr[node + 1];
    bool active = t < 48;
    int head = t >> 4;

    float ax = 0.f, ay = 0.f, az = 0.f, aw = 0.f, den = 0.f;
    int j = rs;
    for (; j + 7 < re; j += 8) {
        int s[8];
#pragma unroll
        for (int u = 0; u < 8; u++) s[u] = g_csr_src[j + u];
        if (active) {
            float w[8];
#pragma unroll
            for (int u = 0; u < 8; u++) w[u] = g_csr_w[(j + u) * 3 + head];
            float4 v[8];
#pragma unroll
            for (int u = 0; u < 8; u++)
                v[u] = *(const float4*)(g_h + (long)s[u] * F1 + t * 4);
#pragma unroll
            for (int u = 0; u < 8; u++) {
                ax += w[u] * v[u].x;
                ay += w[u] * v[u].y;
                az += w[u] * v[u].z;
                aw += w[u] * v[u].w;
                den += w[u];
            }
        }
    }
    for (; j + 1 < re; j += 2) {
        int s0 = g_csr_src[j];
        int s1 = g_csr_src[j + 1];
        if (active) {
            float w0 = g_csr_w[(j + 0) * 3 + head];
            float w1 = g_csr_w[(j + 1) * 3 + head];
            float4 v0 = *(const float4*)(g_h + (long)s0 * F1 + t * 4);
            float4 v1 = *(const float4*)(g_h + (long)s1 * F1 + t * 4);
            ax += w0 * v0.x + w1 * v1.x;
            ay += w0 * v0.y + w1 * v1.y;
            az += w0 * v0.z + w1 * v1.z;
            aw += w0 * v0.w + w1 * v1.w;
            den += w0 + w1;
        }
    }
    if (j < re) {
        int s0 = g_csr_src[j];
        if (active) {
            float  w = g_csr_w[j * 3 + head];
            float4 v = *(const float4*)(g_h + (long)s0 * F1 + t * 4);
            ax += w * v.x; ay += w * v.y; az += w * v.z; aw += w * v.w;
            den += w;
        }
    }
    if (active) {
        float inv = 1.0f / (den + 1e-16f);
        float4 r;
        r.x = elu1(ax * inv);
        r.y = elu1(ay * inv);
        r.z = elu1(az * inv);
        r.w = elu1(aw * inv);
        *(float4*)(g_out1 + (long)node * F1 + t * 4) = r;
    }
}

// ---------------- GEMM2 ----------------------------------------------------
__global__ __launch_bounds__(256) void gemm2_kernel(const float* __restrict__ Wo, int n) {
    __shared__ float As2[16][192];
    __shared__ float Ws[40][196];
    int tid = threadIdx.x;
    int r0  = blockIdx.x * 16;

    for (int i = tid; i < F1 * NCLASS; i += 256) {
        int k = i / NCLASS, c = i % NCLASS;
        Ws[c][k] = Wo[i];
    }
    for (int j = tid; j < 16 * 48; j += 256) {
        int row = j / 48;
        int c4  = (j % 48) * 4;
        int gm  = r0 + row;
        float4 v = make_float4(0.f, 0.f, 0.f, 0.f);
        if (gm < n) v = *(const float4*)(g_out1 + (long)gm * F1 + c4);
        *(float4*)&As2[row][c4] = v;
    }
    __syncthreads();

#pragma unroll
    for (int it = 0; it < 3; it++) {
        int o = tid + it * 256;
        if (o < 16 * NCLASS) {
            int r = o / NCLASS, c = o % NCLASS;
            const float4* a4 = (const float4*)As2[r];
            const float4* w4 = (const float4*)Ws[c];
            float acc = 0.f;
#pragma unroll
            for (int k = 0; k < 48; k++) {
                float4 a = a4[k], w = w4[k];
                acc += a.x * w.x + a.y * w.y + a.z * w.z + a.w * w.w;
            }
            int gm = r0 + r;
            if (gm < n) g_h2[(long)gm * NCLASS + c] = acc;
        }
    }
}

// ---------------- fdot2 ----------------------------------------------------
__global__ void fdot2_kernel(const float* __restrict__ a1o,
                             const float* __restrict__ a2o, int n)
{
    __shared__ float s1[NCLASS], s2[NCLASS];
    int tid = threadIdx.x;
    if (tid < NCLASS) { s1[tid] = a1o[tid]; s2[tid] = a2o[tid]; }
    __syncthreads();
    int node = blockIdx.x * blockDim.x + tid;
    if (node >= n) return;
    const float4* hr = (const float4*)(g_h2 + (long)node * NCLASS);
    float d = 0.f, s = 0.f;
#pragma unroll
    for (int q = 0; q < 10; q++) {
        float4 v = hr[q];
        d += v.x * s1[q * 4 + 0] + v.y * s1[q * 4 + 1] + v.z * s1[q * 4 + 2] + v.w * s1[q * 4 + 3];
        s += v.x * s2[q * 4 + 0] + v.y * s2[q * 4 + 1] + v.z * s2[q * 4 + 2] + v.w * s2[q * 4 + 3];
    }
    g_f2d[node] = d;
    g_f2s[node] = s;
}

// ---------------- layer2 aggregation (fused weights, warp per node) --------
__global__ __launch_bounds__(64) void agg2_kernel(float* __restrict__ out, int n) {
    int node = blockIdx.x * 2 + (threadIdx.x >> 5);
    if (node >= n) return;
    int lane = threadIdx.x & 31;
    int rs = g_rowptr[node];
    int re = g_rowptr[node + 1];
    bool active = lane < 20;
    float fd = g_f2d[node];

    float a0 = 0.f, a1 = 0.f, den = 0.f;
    int j = rs;
    for (; j + 3 < re; j += 4) {
        int s[4];
#pragma unroll
        for (int u = 0; u < 4; u++) s[u] = g_csr_src[j + u];
        float w[4];
        // lanes 0..3 each compute one weight, then broadcast
        float myw = 0.f;
        if (lane < 4) myw = att_w(fd + g_f2s[s[lane]]);
#pragma unroll
        for (int u = 0; u < 4; u++) w[u] = __shfl_sync(0xffffffffu, myw, u);
        if (active) {
#pragma unroll
            for (int u = 0; u < 4; u++) {
                float2 p = *(const float2*)(g_h2 + (long)s[u] * NCLASS + lane * 2);
                a0 += w[u] * p.x;
                a1 += w[u] * p.y;
                den += w[u];
            }
        }
    }
    for (; j < re; j++) {
        int s0 = g_csr_src[j];
        float w = 0.f;
        if (lane == 0) w = att_w(fd + g_f2s[s0]);
        w = __shfl_sync(0xffffffffu, w, 0);
        if (active) {
            float2 p = *(const float2*)(g_h2 + (long)s0 * NCLASS + lane * 2);
            a0 += w * p.x;
            a1 += w * p.y;
            den += w;
        }
    }
    if (active) {
        float inv = 1.0f / (den + 1e-16f);
        float2 r = make_float2(elu1(a0 * inv), elu1(a1 * inv));
        *(float2*)(out + (long)node * NCLASS + lane * 2) = r;
    }
}

// ---------------- launch ---------------------------------------------------
extern "C" void kernel_launch(void* const* d_in, const int* in_sizes, int n_in,
                              void* d_out, int out_size)
{
    const float* x   = (const float*)d_in[0];
    const void*  ei  = d_in[1];
    const float* W   = (const float*)d_in[2];
    const float* a1  = (const float*)d_in[3];
    const float* a2  = (const float*)d_in[4];
    const float* Wo  = (const float*)d_in[5];
    const float* a1o = (const float*)d_in[6];
    const float* a2o = (const float*)d_in[7];
    float* out = (float*)d_out;

    int n = in_sizes[0] / NFEAT;     // 100000
    int E = in_sizes[1] / 2;         // 3300000
    int nb = (n + 1023) / 1024;

    detect_kernel<<<1, 1>>>((const int*)ei);                 // 0
    zero_cnt_kernel<<<(n + 1023) / 1024, 1024>>>(n);         // 1
    count_kernel<<<(E + 255) / 256, 256>>>(ei, E);           // 2

    // gemm1 at launch index 3 -> gets profiled by ncu (-s 3 -c 1 behavior)
    dim3 g1((n + 127) / 128, NHEADS);
    gemm1_tc_kernel<<<g1, 256>>>(x, W, n);                   // 3
    fdot1_kernel<<<(n + 7) / 8, 256>>>(a1, a2, n);           // 4

    scanA_kernel<<<nb, 1024>>>(n);                           // 5
    scanB_kernel<<<1, 128>>>(nb);                            // 6
    scanC_kernel<<<nb, 1024>>>(n);                           // 7

    scatter_kernel<<<(E + 255) / 256, 256>>>(ei, E);         // 8
    agg1_kernel<<<n, 64>>>(n);                               // 9

    gemm2_kernel<<<(n + 15) / 16, 256>>>(Wo, n);             // 10
    fdot2_kernel<<<(n + 255) / 256, 256>>>(a1o, a2o, n);     // 11
    agg2_kernel<<<(n + 1) / 2, 64>>>(out, n);                // 12
}

// round 11
// speedup vs baseline: 1.2485x; 1.0498x over previous
#include <cuda_runtime.h>
#include <cstdint>
#include <math.h>

#define NMAX   100000
#define EMAX   3400000
#define NFEAT  256
#define NHID   64
#define NHEADS 3
#define F1     192      // NHEADS*NHID
#define NCLASS 40

// ---------------- scratch (device globals; no allocations allowed) ----------
__device__ __align__(16) float g_h   [NMAX * F1];
__device__ __align__(16) float g_out1[NMAX * F1];
__device__ __align__(16) float g_h2  [NMAX * NCLASS];
__device__ float g_fd  [NMAX * NHEADS];
__device__ float g_fs  [NMAX * NHEADS];
__device__ float g_f2d [NMAX];
__device__ float g_f2s [NMAX];

__device__ int   g_is64;
__device__ int   g_cnt    [NMAX];
__device__ int   g_rowptr [NMAX + 1];
__device__ int   g_cursor [NMAX];
__device__ int   g_part   [128];
__device__ int   g_total;
__device__ int   g_csr_src[EMAX];
__device__ __align__(16) float g_csr_w [EMAX * 3];

__device__ __forceinline__ float elu1(float x) { return x > 0.f ? x : expm1f(x); }
__device__ __forceinline__ float att_w(float l) {
    float lr = l > 0.f ? l : 0.2f * l;
    return expf(-lr);
}

__device__ __forceinline__ int edge_at(const void* ei, long idx, int is64) {
    if (is64) return (int)((const long long*)ei)[idx];
    return ((const int*)ei)[idx];
}

__device__ __forceinline__ float tf32r(float x) {
    float r;
    asm("cvt.rna.tf32.f32 %0, %1;" : "=f"(r) : "f"(x));
    return r;
}

// ---------------- dtype detection -------------------------------------------
__global__ void detect_kernel(const int* __restrict__ ei32) {
    g_is64 = (ei32[1] == 0 && ei32[3] == 0 && ei32[5] == 0) ? 1 : 0;
}

// ---------------- CSR build --------------------------------------------------
__global__ void zero_cnt_kernel(int n) {
    int i = blockIdx.x * blockDim.x + threadIdx.x;
    if (i < n) g_cnt[i] = 0;
}

__global__ void count_kernel(const void* __restrict__ ei, int E) {
    int e = blockIdx.x * blockDim.x + threadIdx.x;
    if (e >= E) return;
    int is64 = g_is64;
    atomicAdd(&g_cnt[edge_at(ei, e, is64)], 1);
}

__global__ __launch_bounds__(1024) void scanA_kernel(int n) {
    __shared__ int sh[1024];
    int t = threadIdx.x;
    int i = blockIdx.x * 1024 + t;
    int v = (i < n) ? g_cnt[i] : 0;
    sh[t] = v;
    __syncthreads();
#pragma unroll
    for (int off = 1; off < 1024; off <<= 1) {
        int x = sh[t];
        int y = (t >= off) ? sh[t - off] : 0;
        __syncthreads();
        sh[t] = x + y;
        __syncthreads();
    }
    if (i < n) g_rowptr[i] = sh[t] - v;
    if (t == 1023) g_part[blockIdx.x] = sh[1023];
}

__global__ __launch_bounds__(128) void scanB_kernel(int nb) {
    __shared__ int sh[128];
    int t = threadIdx.x;
    int v = (t < nb) ? g_part[t] : 0;
    sh[t] = v;
    __syncthreads();
#pragma unroll
    for (int off = 1; off < 128; off <<= 1) {
        int x = sh[t];
        int y = (t >= off) ? sh[t - off] : 0;
        __syncthreads();
        sh[t] = x + y;
        __syncthreads();
    }
    g_part[t] = sh[t] - v;
    if (t == 127) g_total = sh[127];
}

__global__ __launch_bounds__(1024) void scanC_kernel(int n) {
    int i = blockIdx.x * 1024 + threadIdx.x;
    if (i < n) {
        int r = g_rowptr[i] + g_part[blockIdx.x];
        g_rowptr[i] = r;
        g_cursor[i] = r;
    }
    if (i == 0) g_rowptr[n] = g_total;
}

// scatter + layer1 edge weights
__global__ void scatter_kernel(const void* __restrict__ ei, int E) {
    int e = blockIdx.x * blockDim.x + threadIdx.x;
    if (e >= E) return;
    int is64 = g_is64;
    int dst = edge_at(ei, e, is64);
    int src = edge_at(ei, (long)E + e, is64);
    int pos = atomicAdd(&g_cursor[dst], 1);
    g_csr_src[pos] = src;
#pragma unroll
    for (int h = 0; h < 3; h++)
        g_csr_w[pos * 3 + h] = att_w(g_fd[dst * 3 + h] + g_fs[src * 3 + h]);
}

// ---------------- GEMM1 (tf32 tensor cores, all 3 heads fused) -------------
// g_h[128 rows, 192 cols] per block; warps 2M x 4N (warp tile 64x48).
#define AS_S 36    // A smem row stride
#define BS_S 200   // B smem row stride (192 + 8 pad)
__global__ __launch_bounds__(256) void gemm1_tc_kernel(
    const float* __restrict__ x, const float* __restrict__ W, int n)
{
    __shared__ float As[128 * AS_S];   // 18432 B
    __shared__ float Bs[32 * BS_S];    // 25600 B

    const int m0   = blockIdx.x * 128;
    const int tid  = threadIdx.x;

    const int wid   = tid >> 5;
    const int lane  = tid & 31;
    const int warpM = wid & 1;         // 0..1 -> 64 rows each
    const int warpN = wid >> 1;        // 0..3 -> 48 cols each
    const int g     = lane >> 2;       // 0..7
    const int tg    = lane & 3;        // 0..3

    float c[4][6][4];                  // [mtile][ntile][reg]
#pragma unroll
    for (int mt = 0; mt < 4; mt++)
#pragma unroll
        for (int nt = 0; nt < 6; nt++)
#pragma unroll
            for (int r = 0; r < 4; r++) c[mt][nt][r] = 0.f;

    for (int kt = 0; kt < NFEAT; kt += 32) {
        // A tile 128x32: 1024 float4, 4 per thread
#pragma unroll
        for (int it = 0; it < 4; it++) {
            int j   = tid + it * 256;
            int row = j >> 3;
            int c4  = (j & 7) * 4;
            int gm  = m0 + row;
            float4 v = make_float4(0.f, 0.f, 0.f, 0.f);
            if (gm < n) v = *(const float4*)(x + (long)gm * NFEAT + kt + c4);
            v.x = tf32r(v.x); v.y = tf32r(v.y); v.z = tf32r(v.z); v.w = tf32r(v.w);
            *(float4*)&As[row * AS_S + c4] = v;
        }
        // B tile 32x192 (3 heads x 64): 1536 float4, 6 per thread
#pragma unroll
        for (int it = 0; it < 6; it++) {
            int j    = tid + it * 256;
            int row  = j / 48;
            int cc   = (j % 48) * 4;        // 0..188
            int head = cc >> 6;             // /64
            int hc   = cc & 63;
            float4 v = *(const float4*)(W + head * NFEAT * NHID + (kt + row) * NHID + hc);
            v.x = tf32r(v.x); v.y = tf32r(v.y); v.z = tf32r(v.z); v.w = tf32r(v.w);
            *(float4*)&Bs[row * BS_S + cc] = v;
        }
        __syncthreads();

#pragma unroll
        for (int ks = 0; ks < 4; ks++) {
            const int k0 = ks * 8;
            uint32_t a[4][4];
#pragma unroll
            for (int mt = 0; mt < 4; mt++) {
                int rbase = warpM * 64 + mt * 16;
                a[mt][0] = __float_as_uint(As[(rbase + g)     * AS_S + k0 + tg]);
                a[mt][1] = __float_as_uint(As[(rbase + g + 8) * AS_S + k0 + tg]);
                a[mt][2] = __float_as_uint(As[(rbase + g)     * AS_S + k0 + tg + 4]);
                a[mt][3] = __float_as_uint(As[(rbase + g + 8) * AS_S + k0 + tg + 4]);
            }
#pragma unroll
            for (int nt = 0; nt < 6; nt++) {
                int cbase = warpN * 48 + nt * 8;
                uint32_t b0 = __float_as_uint(Bs[(k0 + tg)     * BS_S + cbase + g]);
                uint32_t b1 = __float_as_uint(Bs[(k0 + tg + 4) * BS_S + cbase + g]);
#pragma unroll
                for (int mt = 0; mt < 4; mt++) {
                    asm volatile(
                        "mma.sync.aligned.m16n8k8.row.col.f32.tf32.tf32.f32 "
                        "{%0,%1,%2,%3}, {%4,%5,%6,%7}, {%8,%9}, {%0,%1,%2,%3};"
                        : "+f"(c[mt][nt][0]), "+f"(c[mt][nt][1]),
                          "+f"(c[mt][nt][2]), "+f"(c[mt][nt][3])
                        : "r"(a[mt][0]), "r"(a[mt][1]), "r"(a[mt][2]), "r"(a[mt][3]),
                          "r"(b0), "r"(b1));
                }
            }
        }
        __syncthreads();
    }

    // epilogue
#pragma unroll
    for (int mt = 0; mt < 4; mt++) {
        int row0 = m0 + warpM * 64 + mt * 16 + g;
#pragma unroll
        for (int nt = 0; nt < 6; nt++) {
            int col = warpN * 48 + nt * 8 + tg * 2;
            if (row0 < n)
                *(float2*)(g_h + (long)row0 * F1 + col) = make_float2(c[mt][nt][0], c[mt][nt][1]);
            if (row0 + 8 < n)
                *(float2*)(g_h + (long)(row0 + 8) * F1 + col) = make_float2(c[mt][nt][2], c[mt][nt][3]);
        }
    }
}

// ---------------- fdot1 ----------------------------------------------------
__global__ __launch_bounds__(256) void fdot1_kernel(
    const float* __restrict__ a1, const float* __restrict__ a2, int n)
{
    __shared__ float s1[F1], s2[F1];
    int tid = threadIdx.x;
    if (tid < F1) { s1[tid] = a1[tid]; s2[tid] = a2[tid]; }
    __syncthreads();

    int node = blockIdx.x * 8 + (tid >> 5);
    int lane = tid & 31;
    bool valid = node < n;
    int nclamp = valid ? node : (n - 1);
    const float* hr = g_h + (long)nclamp * F1;

    float d[3], s[3];
#pragma unroll
    for (int h = 0; h < 3; h++) {
        int i0 = h * 64 + lane;
        int i1 = h * 64 + 32 + lane;
        float v0 = hr[i0], v1 = hr[i1];
        d[h] = v0 * s1[i0] + v1 * s1[i1];
        s[h] = v0 * s2[i0] + v1 * s2[i1];
    }
#pragma unroll
    for (int off = 16; off > 0; off >>= 1) {
#pragma unroll
        for (int h = 0; h < 3; h++) {
            d[h] += __shfl_xor_sync(0xffffffffu, d[h], off);
            s[h] += __shfl_xor_sync(0xffffffffu, s[h], off);
        }
    }
    if (valid && lane == 0) {
#pragma unroll
        for (int h = 0; h < 3; h++) {
            g_fd[node * 3 + h] = d[h];
            g_fs[node * 3 + h] = s[h];
        }
    }
}

// ---------------- layer1 aggregation (fp32 gather, 8-edge unroll) ----------
__global__ __launch_bounds__(64) void agg1_kernel(int n) {
    int node = blockIdx.x;
    if (node >= n) return;
    int t = threadIdx.x;
    int rs = g_rowptr[node];
    int re = g_rowptr[node + 1];
    bool active = t < 48;
    int head = t >> 4;

    float ax = 0.f, ay = 0.f, az = 0.f, aw = 0.f, den = 0.f;
    int j = rs;
    for (; j + 7 < re; j += 8) {
        int s[8];
#pragma unroll
        for (int u = 0; u < 8; u++) s[u] = g_csr_src[j + u];
        if (active) {
            float w[8];
#pragma unroll
            for (int u = 0; u < 8; u++) w[u] = g_csr_w[(j + u) * 3 + head];
            float4 v[8];
#pragma unroll
            for (int u = 0; u < 8; u++)
                v[u] = *(const float4*)(g_h + (long)s[u] * F1 + t * 4);
#pragma unroll
            for (int u = 0; u < 8; u++) {
                ax += w[u] * v[u].x;
                ay += w[u] * v[u].y;
                az += w[u] * v[u].z;
                aw += w[u] * v[u].w;
                den += w[u];
            }
        }
    }
    for (; j + 1 < re; j += 2) {
        int s0 = g_csr_src[j];
        int s1 = g_csr_src[j + 1];
        if (active) {
            float w0 = g_csr_w[(j + 0) * 3 + head];
            float w1 = g_csr_w[(j + 1) * 3 + head];
            float4 v0 = *(const float4*)(g_h + (long)s0 * F1 + t * 4);
            float4 v1 = *(const float4*)(g_h + (long)s1 * F1 + t * 4);
            ax += w0 * v0.x + w1 * v1.x;
            ay += w0 * v0.y + w1 * v1.y;
            az += w0 * v0.z + w1 * v1.z;
            aw += w0 * v0.w + w1 * v1.w;
            den += w0 + w1;
        }
    }
    if (j < re) {
        int s0 = g_csr_src[j];
        if (active) {
            float  w = g_csr_w[j * 3 + head];
            float4 v = *(const float4*)(g_h + (long)s0 * F1 + t * 4);
            ax += w * v.x; ay += w * v.y; az += w * v.z; aw += w * v.w;
            den += w;
        }
    }
    if (active) {
        float inv = 1.0f / (den + 1e-16f);
        float4 r;
        r.x = elu1(ax * inv);
        r.y = elu1(ay * inv);
        r.z = elu1(az * inv);
        r.w = elu1(aw * inv);
        *(float4*)(g_out1 + (long)node * F1 + t * 4) = r;
    }
}

// ---------------- GEMM2 ----------------------------------------------------
__global__ __launch_bounds__(256) void gemm2_kernel(const float* __restrict__ Wo, int n) {
    __shared__ float As2[16][192];
    __shared__ float Ws[40][196];
    int tid = threadIdx.x;
    int r0  = blockIdx.x * 16;

    for (int i = tid; i < F1 * NCLASS; i += 256) {
        int k = i / NCLASS, c = i % NCLASS;
        Ws[c][k] = Wo[i];
    }
    for (int j = tid; j < 16 * 48; j += 256) {
        int row = j / 48;
        int c4  = (j % 48) * 4;
        int gm  = r0 + row;
        float4 v = make_float4(0.f, 0.f, 0.f, 0.f);
        if (gm < n) v = *(const float4*)(g_out1 + (long)gm * F1 + c4);
        *(float4*)&As2[row][c4] = v;
    }
    __syncthreads();

#pragma unroll
    for (int it = 0; it < 3; it++) {
        int o = tid + it * 256;
        if (o < 16 * NCLASS) {
            int r = o / NCLASS, c = o % NCLASS;
            const float4* a4 = (const float4*)As2[r];
            const float4* w4 = (const float4*)Ws[c];
            float acc = 0.f;
#pragma unroll
            for (int k = 0; k < 48; k++) {
                float4 a = a4[k], w = w4[k];
                acc += a.x * w.x + a.y * w.y + a.z * w.z + a.w * w.w;
            }
            int gm = r0 + r;
            if (gm < n) g_h2[(long)gm * NCLASS + c] = acc;
        }
    }
}

// ---------------- fdot2 ----------------------------------------------------
__global__ void fdot2_kernel(const float* __restrict__ a1o,
                             const float* __restrict__ a2o, int n)
{
    __shared__ float s1[NCLASS], s2[NCLASS];
    int tid = threadIdx.x;
    if (tid < NCLASS) { s1[tid] = a1o[tid]; s2[tid] = a2o[tid]; }
    __syncthreads();
    int node = blockIdx.x * blockDim.x + tid;
    if (node >= n) return;
    const float4* hr = (const float4*)(g_h2 + (long)node * NCLASS);
    float d = 0.f, s = 0.f;
#pragma unroll
    for (int q = 0; q < 10; q++) {
        float4 v = hr[q];
        d += v.x * s1[q * 4 + 0] + v.y * s1[q * 4 + 1] + v.z * s1[q * 4 + 2] + v.w * s1[q * 4 + 3];
        s += v.x * s2[q * 4 + 0] + v.y * s2[q * 4 + 1] + v.z * s2[q * 4 + 2] + v.w * s2[q * 4 + 3];
    }
    g_f2d[node] = d;
    g_f2s[node] = s;
}

// ---------------- layer2 aggregation (fused weights, warp per node) --------
__global__ __launch_bounds__(64) void agg2_kernel(float* __restrict__ out, int n) {
    int node = blockIdx.x * 2 + (threadIdx.x >> 5);
    if (node >= n) return;
    int lane = threadIdx.x & 31;
    int rs = g_rowptr[node];
    int re = g_rowptr[node + 1];
    bool active = lane < 20;
    float fd = g_f2d[node];

    float a0 = 0.f, a1 = 0.f, den = 0.f;
    int j = rs;
    for (; j + 3 < re; j += 4) {
        int s[4];
#pragma unroll
        for (int u = 0; u < 4; u++) s[u] = g_csr_src[j + u];
        float w[4];
        float myw = 0.f;
        if (lane < 4) myw = att_w(fd + g_f2s[s[lane]]);
#pragma unroll
        for (int u = 0; u < 4; u++) w[u] = __shfl_sync(0xffffffffu, myw, u);
        if (active) {
#pragma unroll
            for (int u = 0; u < 4; u++) {
                float2 p = *(const float2*)(g_h2 + (long)s[u] * NCLASS + lane * 2);
                a0 += w[u] * p.x;
                a1 += w[u] * p.y;
                den += w[u];
            }
        }
    }
    for (; j < re; j++) {
        int s0 = g_csr_src[j];
        float w = 0.f;
        if (lane == 0) w = att_w(fd + g_f2s[s0]);
        w = __shfl_sync(0xffffffffu, w, 0);
        if (active) {
            float2 p = *(const float2*)(g_h2 + (long)s0 * NCLASS + lane * 2);
            a0 += w * p.x;
            a1 += w * p.y;
            den += w;
        }
    }
    if (active) {
        float inv = 1.0f / (den + 1e-16f);
        float2 r = make_float2(elu1(a0 * inv), elu1(a1 * inv));
        *(float2*)(out + (long)node * NCLASS + lane * 2) = r;
    }
}

// ---------------- launch ---------------------------------------------------
extern "C" void kernel_launch(void* const* d_in, const int* in_sizes, int n_in,
                              void* d_out, int out_size)
{
    const float* x   = (const float*)d_in[0];
    const void*  ei  = d_in[1];
    const float* W   = (const float*)d_in[2];
    const float* a1  = (const float*)d_in[3];
    const float* a2  = (const float*)d_in[4];
    const float* Wo  = (const float*)d_in[5];
    const float* a1o = (const float*)d_in[6];
    const float* a2o = (const float*)d_in[7];
    float* out = (float*)d_out;

    int n = in_sizes[0] / NFEAT;     // 100000
    int E = in_sizes[1] / 2;         // 3300000
    int nb = (n + 1023) / 1024;

    detect_kernel<<<1, 1>>>((const int*)ei);                 // 0
    zero_cnt_kernel<<<(n + 1023) / 1024, 1024>>>(n);         // 1
    count_kernel<<<(E + 255) / 256, 256>>>(ei, E);           // 2

    // gemm1 at launch index 3 -> profiled
    gemm1_tc_kernel<<<(n + 127) / 128, 256>>>(x, W, n);      // 3
    fdot1_kernel<<<(n + 7) / 8, 256>>>(a1, a2, n);           // 4

    scanA_kernel<<<nb, 1024>>>(n);                           // 5
    scanB_kernel<<<1, 128>>>(nb);                            // 6
    scanC_kernel<<<nb, 1024>>>(n);                           // 7

    scatter_kernel<<<(E + 255) / 256, 256>>>(ei, E);         // 8
    agg1_kernel<<<n, 64>>>(n);                               // 9

    gemm2_kernel<<<(n + 15) / 16, 256>>>(Wo, n);             // 10
    fdot2_kernel<<<(n + 255) / 256, 256>>>(a1o, a2o, n);     // 11
    agg2_kernel<<<(n + 1) / 2, 64>>>(out, n);                // 12
}

// round 14
// speedup vs baseline: 1.2697x; 1.0170x over previous
#include <cuda_runtime.h>
#include <cstdint>
#include <math.h>

#define NMAX   100000
#define EMAX   3400000
#define NFEAT  256
#define NHID   64
#define NHEADS 3
#define F1     192      // NHEADS*NHID
#define NCLASS 40

// ---------------- scratch (device globals; no allocations allowed) ----------
__device__ __align__(16) float g_h   [NMAX * F1];
__device__ __align__(16) float g_out1[NMAX * F1];
__device__ __align__(16) float g_h2  [NMAX * NCLASS];
__device__ float g_fd  [NMAX * NHEADS];
__device__ float g_fs  [NMAX * NHEADS];
__device__ float g_f2d [NMAX];
__device__ float g_f2s [NMAX];

__device__ int   g_is64;
__device__ int   g_cnt    [NMAX];
__device__ int   g_rowptr [NMAX + 1];
__device__ int   g_cursor [NMAX];
__device__ int   g_part   [128];
__device__ int   g_total;
__device__ int   g_csr_src[EMAX];
__device__ __align__(16) float g_csr_w [EMAX * 3];

__device__ __forceinline__ float elu1(float x) { return x > 0.f ? x : expm1f(x); }
__device__ __forceinline__ float att_w(float l) {
    float lr = l > 0.f ? l : 0.2f * l;
    return expf(-lr);
}

__device__ __forceinline__ int edge_at(const void* ei, long idx, int is64) {
    if (is64) return (int)((const long long*)ei)[idx];
    return ((const int*)ei)[idx];
}

__device__ __forceinline__ float tf32r(float x) {
    float r;
    asm("cvt.rna.tf32.f32 %0, %1;" : "=f"(r) : "f"(x));
    return r;
}

// ---------------- dtype detection -------------------------------------------
__global__ void detect_kernel(const int* __restrict__ ei32) {
    g_is64 = (ei32[1] == 0 && ei32[3] == 0 && ei32[5] == 0) ? 1 : 0;
}

// ---------------- CSR build --------------------------------------------------
__global__ void zero_cnt_kernel(int n) {
    int i = blockIdx.x * blockDim.x + threadIdx.x;
    if (i < n) g_cnt[i] = 0;
}

__global__ void count_kernel(const void* __restrict__ ei, int E) {
    int e = blockIdx.x * blockDim.x + threadIdx.x;
    if (e >= E) return;
    int is64 = g_is64;
    atomicAdd(&g_cnt[edge_at(ei, e, is64)], 1);
}

__global__ __launch_bounds__(1024) void scanA_kernel(int n) {
    __shared__ int sh[1024];
    int t = threadIdx.x;
    int i = blockIdx.x * 1024 + t;
    int v = (i < n) ? g_cnt[i] : 0;
    sh[t] = v;
    __syncthreads();
#pragma unroll
    for (int off = 1; off < 1024; off <<= 1) {
        int x = sh[t];
        int y = (t >= off) ? sh[t - off] : 0;
        __syncthreads();
        sh[t] = x + y;
        __syncthreads();
    }
    if (i < n) g_rowptr[i] = sh[t] - v;
    if (t == 1023) g_part[blockIdx.x] = sh[1023];
}

__global__ __launch_bounds__(128) void scanB_kernel(int nb) {
    __shared__ int sh[128];
    int t = threadIdx.x;
    int v = (t < nb) ? g_part[t] : 0;
    sh[t] = v;
    __syncthreads();
#pragma unroll
    for (int off = 1; off < 128; off <<= 1) {
        int x = sh[t];
        int y = (t >= off) ? sh[t - off] : 0;
        __syncthreads();
        sh[t] = x + y;
        __syncthreads();
    }
    g_part[t] = sh[t] - v;
    if (t == 127) g_total = sh[127];
}

__global__ __launch_bounds__(1024) void scanC_kernel(int n) {
    int i = blockIdx.x * 1024 + threadIdx.x;
    if (i < n) {
        int r = g_rowptr[i] + g_part[blockIdx.x];
        g_rowptr[i] = r;
        g_cursor[i] = r;
    }
    if (i == 0) g_rowptr[n] = g_total;
}

// scatter + layer1 edge weights
__global__ void scatter_kernel(const void* __restrict__ ei, int E) {
    int e = blockIdx.x * blockDim.x + threadIdx.x;
    if (e >= E) return;
    int is64 = g_is64;
    int dst = edge_at(ei, e, is64);
    int src = edge_at(ei, (long)E + e, is64);
    int pos = atomicAdd(&g_cursor[dst], 1);
    g_csr_src[pos] = src;
#pragma unroll
    for (int h = 0; h < 3; h++)
        g_csr_w[pos * 3 + h] = att_w(g_fd[dst * 3 + h] + g_fs[src * 3 + h]);
}

// ---------------- GEMM1 (tf32 TC, 3 heads fused, reg-staged 2-stage) -------
// Block: 128x192 output; BK=16; warps 2M x 4N (warp tile 64x48).
#define AS_S2 20    // A smem row stride (16 + 4 pad)
#define BS_S 200    // B smem row stride (192 + 8 pad)
#define NKT 16      // 256 / 16
__global__ __launch_bounds__(256) void gemm1_tc_kernel(
    const float* __restrict__ x, const float* __restrict__ W, int n)
{
    __shared__ float As[2][128 * AS_S2];   // 2 x 10240 B
    __shared__ float Bs[2][16 * BS_S];     // 2 x 12800 B

    const int m0   = blockIdx.x * 128;
    const int tid  = threadIdx.x;

    const int wid   = tid >> 5;
    const int lane  = tid & 31;
    const int warpM = wid & 1;
    const int warpN = wid >> 1;
    const int g     = lane >> 2;
    const int tg    = lane & 3;

    // per-thread load coordinates (fixed across tiles)
    // A: 2 float4 per thread
    const int arow0 = tid >> 2;              // j=tid
    const int ac40  = (tid & 3) * 4;
    const int arow1 = (tid + 256) >> 2;      // j=tid+256
    const int ac41  = ((tid + 256) & 3) * 4;
    // B: 3 float4 per thread
    int brow[3], bcc[3];
    const float* bsrc[3];
#pragma unroll
    for (int it = 0; it < 3; it++) {
        int j    = tid + it * 256;
        brow[it] = j / 48;
        int cc   = (j % 48) * 4;
        bcc[it]  = cc;
        int head = cc >> 6;
        int hc   = cc & 63;
        bsrc[it] = W + head * NFEAT * NHID + brow[it] * NHID + hc;
    }

    float c[4][6][4];
#pragma unroll
    for (int mt = 0; mt < 4; mt++)
#pragma unroll
        for (int nt = 0; nt < 6; nt++)
#pragma unroll
            for (int r = 0; r < 4; r++) c[mt][nt][r] = 0.f;

    float4 ra0, ra1, rb[3];
    // load tile 0
    {
        int gm0 = m0 + arow0, gm1 = m0 + arow1;
        ra0 = (gm0 < n) ? *(const float4*)(x + (long)gm0 * NFEAT + ac40)
                        : make_float4(0.f, 0.f, 0.f, 0.f);
        ra1 = (gm1 < n) ? *(const float4*)(x + (long)gm1 * NFEAT + ac41)
                        : make_float4(0.f, 0.f, 0.f, 0.f);
#pragma unroll
        for (int it = 0; it < 3; it++) rb[it] = *(const float4*)(bsrc[it]);
    }
    // store tile 0 -> buf 0 (tf32-rounded)
    {
        float4 v;
        v = ra0; v.x = tf32r(v.x); v.y = tf32r(v.y); v.z = tf32r(v.z); v.w = tf32r(v.w);
        *(float4*)&As[0][arow0 * AS_S2 + ac40] = v;
        v = ra1; v.x = tf32r(v.x); v.y = tf32r(v.y); v.z = tf32r(v.z); v.w = tf32r(v.w);
        *(float4*)&As[0][arow1 * AS_S2 + ac41] = v;
#pragma unroll
        for (int it = 0; it < 3; it++) {
            v = rb[it]; v.x = tf32r(v.x); v.y = tf32r(v.y); v.z = tf32r(v.z); v.w = tf32r(v.w);
            *(float4*)&Bs[0][brow[it] * BS_S + bcc[it]] = v;
        }
    }
    __syncthreads();

    for (int t = 0; t < NKT; t++) {
        const int st = t & 1;
        // prefetch next tile into registers (LDGs issued before compute)
        if (t + 1 < NKT) {
            int kt = (t + 1) * 16;
            int gm0 = m0 + arow0, gm1 = m0 + arow1;
            ra0 = (gm0 < n) ? *(const float4*)(x + (long)gm0 * NFEAT + kt + ac40)
                            : make_float4(0.f, 0.f, 0.f, 0.f);
            ra1 = (gm1 < n) ? *(const float4*)(x + (long)gm1 * NFEAT + kt + ac41)
                            : make_float4(0.f, 0.f, 0.f, 0.f);
#pragma unroll
            for (int it = 0; it < 3; it++) rb[it] = *(const float4*)(bsrc[it] + kt * NHID);
        }

        const float* Asb = As[st];
        const float* Bsb = Bs[st];
#pragma unroll
        for (int ks = 0; ks < 2; ks++) {
            const int k0 = ks * 8;
            uint32_t a[4][4];
#pragma unroll
            for (int mt = 0; mt < 4; mt++) {
                int rbase = warpM * 64 + mt * 16;
                a[mt][0] = __float_as_uint(Asb[(rbase + g)     * AS_S2 + k0 + tg]);
                a[mt][1] = __float_as_uint(Asb[(rbase + g + 8) * AS_S2 + k0 + tg]);
                a[mt][2] = __float_as_uint(Asb[(rbase + g)     * AS_S2 + k0 + tg + 4]);
                a[mt][3] = __float_as_uint(Asb[(rbase + g + 8) * AS_S2 + k0 + tg + 4]);
            }
#pragma unroll
            for (int nt = 0; nt < 6; nt++) {
                int cbase = warpN * 48 + nt * 8;
                uint32_t b0 = __float_as_uint(Bsb[(k0 + tg)     * BS_S + cbase + g]);
                uint32_t b1 = __float_as_uint(Bsb[(k0 + tg + 4) * BS_S + cbase + g]);
#pragma unroll
                for (int mt = 0; mt < 4; mt++) {
                    asm volatile(
                        "mma.sync.aligned.m16n8k8.row.col.f32.tf32.tf32.f32 "
                        "{%0,%1,%2,%3}, {%4,%5,%6,%7}, {%8,%9}, {%0,%1,%2,%3};"
                        : "+f"(c[mt][nt][0]), "+f"(c[mt][nt][1]),
                          "+f"(c[mt][nt][2]), "+f"(c[mt][nt][3])
                        : "r"(a[mt][0]), "r"(a[mt][1]), "r"(a[mt][2]), "r"(a[mt][3]),
                          "r"(b0), "r"(b1));
                }
            }
        }

        if (t + 1 < NKT) {
            // write next tile to the other buffer; its last readers were
            // iteration t-1, fenced by that iteration's __syncthreads.
            const int ns = (t + 1) & 1;
            float4 v;
            v = ra0; v.x = tf32r(v.x); v.y = tf32r(v.y); v.z = tf32r(v.z); v.w = tf32r(v.w);
            *(float4*)&As[ns][arow0 * AS_S2 + ac40] = v;
            v = ra1; v.x = tf32r(v.x); v.y = tf32r(v.y); v.z = tf32r(v.z); v.w = tf32r(v.w);
            *(float4*)&As[ns][arow1 * AS_S2 + ac41] = v;
#pragma unroll
            for (int it = 0; it < 3; it++) {
                v = rb[it]; v.x = tf32r(v.x); v.y = tf32r(v.y); v.z = tf32r(v.z); v.w = tf32r(v.w);
                *(float4*)&Bs[ns][brow[it] * BS_S + bcc[it]] = v;
            }
            __syncthreads();
        }
    }

    // epilogue
#pragma unroll
    for (int mt = 0; mt < 4; mt++) {
        int row0 = m0 + warpM * 64 + mt * 16 + g;
#pragma unroll
        for (int nt = 0; nt < 6; nt++) {
            int col = warpN * 48 + nt * 8 + tg * 2;
            if (row0 < n)
                *(float2*)(g_h + (long)row0 * F1 + col) = make_float2(c[mt][nt][0], c[mt][nt][1]);
            if (row0 + 8 < n)
                *(float2*)(g_h + (long)(row0 + 8) * F1 + col) = make_float2(c[mt][nt][2], c[mt][nt][3]);
        }
    }
}

// ---------------- fdot1 ----------------------------------------------------
__global__ __launch_bounds__(256) void fdot1_kernel(
    const float* __restrict__ a1, const float* __restrict__ a2, int n)
{
    __shared__ float s1[F1], s2[F1];
    int tid = threadIdx.x;
    if (tid < F1) { s1[tid] = a1[tid]; s2[tid] = a2[tid]; }
    __syncthreads();

    int node = blockIdx.x * 8 + (tid >> 5);
    int lane = tid & 31;
    bool valid = node < n;
    int nclamp = valid ? node : (n - 1);
    const float* hr = g_h + (long)nclamp * F1;

    float d[3], s[3];
#pragma unroll
    for (int h = 0; h < 3; h++) {
        int i0 = h * 64 + lane;
        int i1 = h * 64 + 32 + lane;
        float v0 = hr[i0], v1 = hr[i1];
        d[h] = v0 * s1[i0] + v1 * s1[i1];
        s[h] = v0 * s2[i0] + v1 * s2[i1];
    }
#pragma unroll
    for (int off = 16; off > 0; off >>= 1) {
#pragma unroll
        for (int h = 0; h < 3; h++) {
            d[h] += __shfl_xor_sync(0xffffffffu, d[h], off);
            s[h] += __shfl_xor_sync(0xffffffffu, s[h], off);
        }
    }
    if (valid && lane == 0) {
#pragma unroll
        for (int h = 0; h < 3; h++) {
            g_fd[node * 3 + h] = d[h];
            g_fs[node * 3 + h] = s[h];
        }
    }
}

// ---------------- layer1 aggregation (fp32 gather, 8-edge unroll) ----------
__global__ __launch_bounds__(64) void agg1_kernel(int n) {
    int node = blockIdx.x;
    if (node >= n) return;
    int t = threadIdx.x;
    int rs = g_rowptr[node];
    int re = g_rowptr[node + 1];
    bool active = t < 48;
    int head = t >> 4;

    float ax = 0.f, ay = 0.f, az = 0.f, aw = 0.f, den = 0.f;
    int j = rs;
    for (; j + 7 < re; j += 8) {
        int s[8];
#pragma unroll
        for (int u = 0; u < 8; u++) s[u] = g_csr_src[j + u];
        if (active) {
            float w[8];
#pragma unroll
            for (int u = 0; u < 8; u++) w[u] = g_csr_w[(j + u) * 3 + head];
            float4 v[8];
#pragma unroll
            for (int u = 0; u < 8; u++)
                v[u] = *(const float4*)(g_h + (long)s[u] * F1 + t * 4);
#pragma unroll
            for (int u = 0; u < 8; u++) {
                ax += w[u] * v[u].x;
                ay += w[u] * v[u].y;
                az += w[u] * v[u].z;
                aw += w[u] * v[u].w;
                den += w[u];
            }
        }
    }
    for (; j + 1 < re; j += 2) {
        int s0 = g_csr_src[j];
        int s1 = g_csr_src[j + 1];
        if (active) {
            float w0 = g_csr_w[(j + 0) * 3 + head];
            float w1 = g_csr_w[(j + 1) * 3 + head];
            float4 v0 = *(const float4*)(g_h + (long)s0 * F1 + t * 4);
            float4 v1 = *(const float4*)(g_h + (long)s1 * F1 + t * 4);
            ax += w0 * v0.x + w1 * v1.x;
            ay += w0 * v0.y + w1 * v1.y;
            az += w0 * v0.z + w1 * v1.z;
            aw += w0 * v0.w + w1 * v1.w;
            den += w0 + w1;
        }
    }
    if (j < re) {
        int s0 = g_csr_src[j];
        if (active) {
            float  w = g_csr_w[j * 3 + head];
            float4 v = *(const float4*)(g_h + (long)s0 * F1 + t * 4);
            ax += w * v.x; ay += w * v.y; az += w * v.z; aw += w * v.w;
            den += w;
        }
    }
    if (active) {
        float inv = 1.0f / (den + 1e-16f);
        float4 r;
        r.x = elu1(ax * inv);
        r.y = elu1(ay * inv);
        r.z = elu1(az * inv);
        r.w = elu1(aw * inv);
        *(float4*)(g_out1 + (long)node * F1 + t * 4) = r;
    }
}

// ---------------- GEMM2 ----------------------------------------------------
__global__ __launch_bounds__(256) void gemm2_kernel(const float* __restrict__ Wo, int n) {
    __shared__ float As2[16][192];
    __shared__ float Ws[40][196];
    int tid = threadIdx.x;
    int r0  = blockIdx.x * 16;

    for (int i = tid; i < F1 * NCLASS; i += 256) {
        int k = i / NCLASS, c = i % NCLASS;
        Ws[c][k] = Wo[i];
    }
    for (int j = tid; j < 16 * 48; j += 256) {
        int row = j / 48;
        int c4  = (j % 48) * 4;
        int gm  = r0 + row;
        float4 v = make_float4(0.f, 0.f, 0.f, 0.f);
        if (gm < n) v = *(const float4*)(g_out1 + (long)gm * F1 + c4);
        *(float4*)&As2[row][c4] = v;
    }
    __syncthreads();

#pragma unroll
    for (int it = 0; it < 3; it++) {
        int o = tid + it * 256;
        if (o < 16 * NCLASS) {
            int r = o / NCLASS, c = o % NCLASS;
            const float4* a4 = (const float4*)As2[r];
            const float4* w4 = (const float4*)Ws[c];
            float acc = 0.f;
#pragma unroll
            for (int k = 0; k < 48; k++) {
                float4 a = a4[k], w = w4[k];
                acc += a.x * w.x + a.y * w.y + a.z * w.z + a.w * w.w;
            }
            int gm = r0 + r;
            if (gm < n) g_h2[(long)gm * NCLASS + c] = acc;
        }
    }
}

// ---------------- fdot2 ----------------------------------------------------
__global__ void fdot2_kernel(const float* __restrict__ a1o,
                             const float* __restrict__ a2o, int n)
{
    __shared__ float s1[NCLASS], s2[NCLASS];
    int tid = threadIdx.x;
    if (tid < NCLASS) { s1[tid] = a1o[tid]; s2[tid] = a2o[tid]; }
    __syncthreads();
    int node = blockIdx.x * blockDim.x + tid;
    if (node >= n) return;
    const float4* hr = (const float4*)(g_h2 + (long)node * NCLASS);
    float d = 0.f, s = 0.f;
#pragma unroll
    for (int q = 0; q < 10; q++) {
        float4 v = hr[q];
        d += v.x * s1[q * 4 + 0] + v.y * s1[q * 4 + 1] + v.z * s1[q * 4 + 2] + v.w * s1[q * 4 + 3];
        s += v.x * s2[q * 4 + 0] + v.y * s2[q * 4 + 1] + v.z * s2[q * 4 + 2] + v.w * s2[q * 4 + 3];
    }
    g_f2d[node] = d;
    g_f2s[node] = s;
}

// ---------------- layer2 aggregation (fused weights, warp per node) --------
__global__ __launch_bounds__(64) void agg2_kernel(float* __restrict__ out, int n) {
    int node = blockIdx.x * 2 + (threadIdx.x >> 5);
    if (node >= n) return;
    int lane = threadIdx.x & 31;
    int rs = g_rowptr[node];
    int re = g_rowptr[node + 1];
    bool active = lane < 20;
    float fd = g_f2d[node];

    float a0 = 0.f, a1 = 0.f, den = 0.f;
    int j = rs;
    for (; j + 3 < re; j += 4) {
        int s[4];
#pragma unroll
        for (int u = 0; u < 4; u++) s[u] = g_csr_src[j + u];
        float w[4];
        float myw = 0.f;
        if (lane < 4) myw = att_w(fd + g_f2s[s[lane]]);
#pragma unroll
        for (int u = 0; u < 4; u++) w[u] = __shfl_sync(0xffffffffu, myw, u);
        if (active) {
#pragma unroll
            for (int u = 0; u < 4; u++) {
                float2 p = *(const float2*)(g_h2 + (long)s[u] * NCLASS + lane * 2);
                a0 += w[u] * p.x;
                a1 += w[u] * p.y;
                den += w[u];
            }
        }
    }
    for (; j < re; j++) {
        int s0 = g_csr_src[j];
        float w = 0.f;
        if (lane == 0) w = att_w(fd + g_f2s[s0]);
        w = __shfl_sync(0xffffffffu, w, 0);
        if (active) {
            float2 p = *(const float2*)(g_h2 + (long)s0 * NCLASS + lane * 2);
            a0 += w * p.x;
            a1 += w * p.y;
            den += w;
        }
    }
    if (active) {
        float inv = 1.0f / (den + 1e-16f);
        float2 r = make_float2(elu1(a0 * inv), elu1(a1 * inv));
        *(float2*)(out + (long)node * NCLASS + lane * 2) = r;
    }
}

// ---------------- launch ---------------------------------------------------
extern "C" void kernel_launch(void* const* d_in, const int* in_sizes, int n_in,
                              void* d_out, int out_size)
{
    const float* x   = (const float*)d_in[0];
    const void*  ei  = d_in[1];
    const float* W   = (const float*)d_in[2];
    const float* a1  = (const float*)d_in[3];
    const float* a2  = (const float*)d_in[4];
    const float* Wo  = (const float*)d_in[5];
    const float* a1o = (const float*)d_in[6];
    const float* a2o = (const float*)d_in[7];
    float* out = (float*)d_out;

    int n = in_sizes[0] / NFEAT;     // 100000
    int E = in_sizes[1] / 2;         // 3300000
    int nb = (n + 1023) / 1024;

    detect_kernel<<<1, 1>>>((const int*)ei);                 // 0
    zero_cnt_kernel<<<(n + 1023) / 1024, 1024>>>(n);         // 1
    count_kernel<<<(E + 255) / 256, 256>>>(ei, E);           // 2

    // gemm1 at launch index 3 -> profiled
    gemm1_tc_kernel<<<(n + 127) / 128, 256>>>(x, W, n);      // 3
    fdot1_kernel<<<(n + 7) / 8, 256>>>(a1, a2, n);           // 4

    scanA_kernel<<<nb, 1024>>>(n);                           // 5
    scanB_kernel<<<1, 128>>>(nb);                            // 6
    scanC_kernel<<<nb, 1024>>>(n);                           // 7

    scatter_kernel<<<(E + 255) / 256, 256>>>(ei, E);         // 8
    agg1_kernel<<<n, 64>>>(n);                               // 9

    gemm2_kernel<<<(n + 15) / 16, 256>>>(Wo, n);             // 10
    fdot2_kernel<<<(n + 255) / 256, 256>>>(a1o, a2o, n);     // 11
    agg2_kernel<<<(n + 1) / 2, 64>>>(out, n);                // 12
}